// round 3
// baseline (speedup 1.0000x reference)
#include <cuda_runtime.h>
#include <cstdint>
#include <cstddef>

#define B_   8
#define N_   8192
#define S_   2048
#define K_   32
#define F_   64
#define CIN_ 67
#define EPSF 1e-5f

// scratch: group indices (-1 padded), 2 MB static device array
__device__ int g_gidx[B_ * S_ * K_];

// ---------------------------------------------------------------------------
// Kernel 1: farthest point sampling. One CTA per batch, 1024 threads,
// 8 points per thread held in registers. Sequential argmax chain.
// Distance arithmetic uses separately-rounded mul/add (no fma contraction)
// in canonical order ((dx*dx + dy*dy) + dz*dz) to bit-match XLA.
// ---------------------------------------------------------------------------
#define NPT 8
__global__ __launch_bounds__(1024, 1)
void fps_kernel(const float* __restrict__ xyzs, float* __restrict__ outc)
{
    extern __shared__ float sm1[];
    float* sx = sm1;
    float* sy = sm1 + N_;
    float* sz = sm1 + 2 * N_;
    __shared__ float swv[32];
    __shared__ int   swi[32];
    __shared__ int   s_best;

    const int b   = blockIdx.x;
    const int tid = threadIdx.x;
    const float* xyz = xyzs + (size_t)b * N_ * 3;

    float px[NPT], py[NPT], pz[NPT], mind[NPT];
#pragma unroll
    for (int j = 0; j < NPT; j++) {
        int i = tid + j * 1024;
        float X = xyz[i * 3 + 0];
        float Y = xyz[i * 3 + 1];
        float Z = xyz[i * 3 + 2];
        px[j] = X; py[j] = Y; pz[j] = Z;
        sx[i] = X; sy[i] = Y; sz[i] = Z;
        mind[j] = 1e10f;
    }
    __syncthreads();

    float cx = sx[0], cy = sy[0], cz = sz[0];
    if (tid == 0) {
        float* o = outc + (size_t)b * S_ * 3;
        o[0] = cx; o[1] = cy; o[2] = cz;
    }

    for (int s = 1; s < S_; s++) {
        float bv = -1.0f;
        int   bi = 0;
#pragma unroll
        for (int j = 0; j < NPT; j++) {
            float dx = __fsub_rn(px[j], cx);
            float dy = __fsub_rn(py[j], cy);
            float dz = __fsub_rn(pz[j], cz);
            // exactly ((dx*dx + dy*dy) + dz*dz), each op rn, no contraction
            float d  = __fadd_rn(__fadd_rn(__fmul_rn(dx, dx), __fmul_rn(dy, dy)),
                                 __fmul_rn(dz, dz));
            float m  = fminf(mind[j], d);
            mind[j]  = m;
            if (m > bv) { bv = m; bi = tid + j * 1024; }  // ascending idx -> keeps lowest on tie
        }
        // warp reduce (val, idx), tie -> lower idx
#pragma unroll
        for (int off = 16; off > 0; off >>= 1) {
            float ov = __shfl_down_sync(0xffffffffu, bv, off);
            int   oi = __shfl_down_sync(0xffffffffu, bi, off);
            if (ov > bv || (ov == bv && oi < bi)) { bv = ov; bi = oi; }
        }
        if ((tid & 31) == 0) { swv[tid >> 5] = bv; swi[tid >> 5] = bi; }
        __syncthreads();
        if (tid < 32) {
            float v = swv[tid];
            int   i2 = swi[tid];
#pragma unroll
            for (int off = 16; off > 0; off >>= 1) {
                float ov = __shfl_down_sync(0xffffffffu, v, off);
                int   oi = __shfl_down_sync(0xffffffffu, i2, off);
                if (ov > v || (ov == v && oi < i2)) { v = ov; i2 = oi; }
            }
            if (tid == 0) {
                s_best = i2;
                float* o = outc + ((size_t)b * S_ + s) * 3;
                o[0] = sx[i2]; o[1] = sy[i2]; o[2] = sz[i2];
            }
        }
        __syncthreads();
        int bidx = s_best;
        cx = sx[bidx]; cy = sy[bidx]; cz = sz[bidx];
    }
}

// ---------------------------------------------------------------------------
// Kernel 2: ball query. Each thread owns one center; points broadcast from
// SMEM (float4: x,y,z,|x|^2). First-K-by-index semantics via sequential scan.
// d2 = (|c|^2 + |x|^2) - 2*((cx*px + cy*py) + cz*pz), uncontracted rn ops,
// mirroring the reference's  c^2 + x^2 - 2*einsum  structure.
// ---------------------------------------------------------------------------
__global__ __launch_bounds__(128)
void ball_kernel(const float* __restrict__ xyzs, const float* __restrict__ centers)
{
    extern __shared__ float4 sp[];   // [N_] : 128 KB

    const int cbase = blockIdx.x * 128;
    const int b     = cbase >> 11;           // / 2048
    const float* xyz = xyzs + (size_t)b * N_ * 3;

    for (int i = threadIdx.x; i < N_; i += 128) {
        float X = xyz[i * 3 + 0];
        float Y = xyz[i * 3 + 1];
        float Z = xyz[i * 3 + 2];
        float nrm = __fadd_rn(__fadd_rn(__fmul_rn(X, X), __fmul_rn(Y, Y)),
                              __fmul_rn(Z, Z));
        sp[i] = make_float4(X, Y, Z, nrm);
    }
    __syncthreads();

    const int ci = cbase + threadIdx.x;
    const float* c = centers + (size_t)ci * 3;
    const float cx = c[0], cy = c[1], cz = c[2];
    const float cc = __fadd_rn(__fadd_rn(__fmul_rn(cx, cx), __fmul_rn(cy, cy)),
                               __fmul_rn(cz, cz));
    const float R2 = 0.2f * 0.2f;

    int cnt = 0;
    for (int n = 0; n < N_; n++) {
        float4 p = sp[n];
        float dot = __fadd_rn(__fadd_rn(__fmul_rn(cx, p.x), __fmul_rn(cy, p.y)),
                              __fmul_rn(cz, p.z));
        float d2  = __fsub_rn(__fadd_rn(cc, p.w), __fmul_rn(2.0f, dot));
        if (d2 <= R2 && cnt < K_) {
            g_gidx[(size_t)ci * K_ + cnt] = n;
            cnt++;
        }
        if ((n & 63) == 63 && __all_sync(0xffffffffu, cnt >= K_)) break;
    }
    for (int t = cnt; t < K_; t++) g_gidx[(size_t)ci * K_ + t] = -1;
}

// ---------------------------------------------------------------------------
// Kernel 3: gather + 3-layer MLP (BN folded) + max over K.
// 128 threads = 4 warps per block, one center per warp. lane = k slot.
// Weights transposed+BN-folded into SMEM once per block; broadcast LDS.128.
// grid = 16384/4 = 4096 blocks.
// ---------------------------------------------------------------------------
__global__ __launch_bounds__(128)
void mlp_kernel(const float* __restrict__ xyzs, const float* __restrict__ feats,
                const float* __restrict__ w1, const float* __restrict__ b1,
                const float* __restrict__ g1, const float* __restrict__ bt1,
                const float* __restrict__ m1, const float* __restrict__ v1,
                const float* __restrict__ w2, const float* __restrict__ b2,
                const float* __restrict__ g2, const float* __restrict__ bt2,
                const float* __restrict__ m2, const float* __restrict__ v2,
                const float* __restrict__ w3, const float* __restrict__ b3,
                const float* __restrict__ g3, const float* __restrict__ bt3,
                const float* __restrict__ m3, const float* __restrict__ v3,
                const float* __restrict__ centers, float* __restrict__ outf)
{
    extern __shared__ float sm3[];
    float* sW1 = sm3;                 // [67][64] transposed: sW1[c*64+o]
    float* sW2 = sW1 + CIN_ * 64;     // [64][64]
    float* sW3 = sW2 + 64 * 64;       // [64][128]
    float* sB1 = sW3 + 64 * 128;      // 64
    float* sB2 = sB1 + 64;            // 64
    float* sB3 = sB2 + 64;            // 128
    float* sS  = sB3 + 128;           // 256 scales: s1[64] s2[64] s3[128]

    const int tid = threadIdx.x;

    if (tid < 64) {
        float s = g1[tid] * rsqrtf(v1[tid] + EPSF);
        sS[tid] = s;
        sB1[tid] = (b1[tid] - m1[tid]) * s + bt1[tid];
    } else {
        int o = tid - 64;
        float s = g2[o] * rsqrtf(v2[o] + EPSF);
        sS[64 + o] = s;
        sB2[o] = (b2[o] - m2[o]) * s + bt2[o];
    }
    {
        float s = g3[tid] * rsqrtf(v3[tid] + EPSF);
        sS[128 + tid] = s;
        sB3[tid] = (b3[tid] - m3[tid]) * s + bt3[tid];
    }
    __syncthreads();

    for (int i = tid; i < CIN_ * 64; i += 128) {
        int c = i >> 6, o = i & 63;
        sW1[i] = w1[o * CIN_ + c] * sS[o];
    }
    for (int i = tid; i < 64 * 64; i += 128) {
        int c = i >> 6, o = i & 63;
        sW2[i] = w2[o * 64 + c] * sS[64 + o];
    }
    for (int i = tid; i < 64 * 128; i += 128) {
        int c = i >> 7, o = i & 127;
        sW3[i] = w3[o * 64 + c] * sS[128 + o];
    }
    __syncthreads();

    const int warp = tid >> 5;
    const int lane = tid & 31;
    const int ci   = blockIdx.x * 4 + warp;
    const int b    = ci >> 11;   // / 2048

    // gather input row for this lane's k slot
    const int ig = g_gidx[(size_t)ci * K_ + lane];
    float x[CIN_];
    if (ig >= 0) {
        const float* ctr = centers + (size_t)ci * 3;
        const float* p   = xyzs + ((size_t)b * N_ + ig) * 3;
        x[0] = p[0] - ctr[0];
        x[1] = p[1] - ctr[1];
        x[2] = p[2] - ctr[2];
        const float4* f4 = (const float4*)(feats + ((size_t)b * N_ + ig) * F_);
#pragma unroll
        for (int q = 0; q < 16; q++) {
            float4 t = f4[q];
            x[3 + 4 * q + 0] = t.x;
            x[3 + 4 * q + 1] = t.y;
            x[3 + 4 * q + 2] = t.z;
            x[3 + 4 * q + 3] = t.w;
        }
    } else {
#pragma unroll
        for (int q = 0; q < CIN_; q++) x[q] = 0.0f;
    }

    // layer 1: 67 -> 64
    float y1[64];
#pragma unroll
    for (int ch = 0; ch < 4; ch++) {
        float a[16];
#pragma unroll
        for (int t = 0; t < 16; t++) a[t] = sB1[ch * 16 + t];
#pragma unroll
        for (int c = 0; c < CIN_; c++) {
            float xv = x[c];
            const float4* wp = (const float4*)&sW1[c * 64 + ch * 16];
            float4 w0 = wp[0], wA = wp[1], wB = wp[2], wC = wp[3];
            a[0]  = fmaf(xv, w0.x, a[0]);  a[1]  = fmaf(xv, w0.y, a[1]);
            a[2]  = fmaf(xv, w0.z, a[2]);  a[3]  = fmaf(xv, w0.w, a[3]);
            a[4]  = fmaf(xv, wA.x, a[4]);  a[5]  = fmaf(xv, wA.y, a[5]);
            a[6]  = fmaf(xv, wA.z, a[6]);  a[7]  = fmaf(xv, wA.w, a[7]);
            a[8]  = fmaf(xv, wB.x, a[8]);  a[9]  = fmaf(xv, wB.y, a[9]);
            a[10] = fmaf(xv, wB.z, a[10]); a[11] = fmaf(xv, wB.w, a[11]);
            a[12] = fmaf(xv, wC.x, a[12]); a[13] = fmaf(xv, wC.y, a[13]);
            a[14] = fmaf(xv, wC.z, a[14]); a[15] = fmaf(xv, wC.w, a[15]);
        }
#pragma unroll
        for (int t = 0; t < 16; t++) y1[ch * 16 + t] = fmaxf(a[t], 0.0f);
    }

    // layer 2: 64 -> 64
    float y2[64];
#pragma unroll
    for (int ch = 0; ch < 4; ch++) {
        float a[16];
#pragma unroll
        for (int t = 0; t < 16; t++) a[t] = sB2[ch * 16 + t];
#pragma unroll
        for (int c = 0; c < 64; c++) {
            float xv = y1[c];
            const float4* wp = (const float4*)&sW2[c * 64 + ch * 16];
            float4 w0 = wp[0], wA = wp[1], wB = wp[2], wC = wp[3];
            a[0]  = fmaf(xv, w0.x, a[0]);  a[1]  = fmaf(xv, w0.y, a[1]);
            a[2]  = fmaf(xv, w0.z, a[2]);  a[3]  = fmaf(xv, w0.w, a[3]);
            a[4]  = fmaf(xv, wA.x, a[4]);  a[5]  = fmaf(xv, wA.y, a[5]);
            a[6]  = fmaf(xv, wA.z, a[6]);  a[7]  = fmaf(xv, wA.w, a[7]);
            a[8]  = fmaf(xv, wB.x, a[8]);  a[9]  = fmaf(xv, wB.y, a[9]);
            a[10] = fmaf(xv, wB.z, a[10]); a[11] = fmaf(xv, wB.w, a[11]);
            a[12] = fmaf(xv, wC.x, a[12]); a[13] = fmaf(xv, wC.y, a[13]);
            a[14] = fmaf(xv, wC.z, a[14]); a[15] = fmaf(xv, wC.w, a[15]);
        }
#pragma unroll
        for (int t = 0; t < 16; t++) y2[ch * 16 + t] = fmaxf(a[t], 0.0f);
    }

    // layer 3: 64 -> 128, relu, warp max over K, store
    float* op = outf + (size_t)ci * 128;
#pragma unroll
    for (int ch = 0; ch < 8; ch++) {
        float a[16];
#pragma unroll
        for (int t = 0; t < 16; t++) a[t] = sB3[ch * 16 + t];
#pragma unroll
        for (int c = 0; c < 64; c++) {
            float xv = y2[c];
            const float4* wp = (const float4*)&sW3[c * 128 + ch * 16];
            float4 w0 = wp[0], wA = wp[1], wB = wp[2], wC = wp[3];
            a[0]  = fmaf(xv, w0.x, a[0]);  a[1]  = fmaf(xv, w0.y, a[1]);
            a[2]  = fmaf(xv, w0.z, a[2]);  a[3]  = fmaf(xv, w0.w, a[3]);
            a[4]  = fmaf(xv, wA.x, a[4]);  a[5]  = fmaf(xv, wA.y, a[5]);
            a[6]  = fmaf(xv, wA.z, a[6]);  a[7]  = fmaf(xv, wA.w, a[7]);
            a[8]  = fmaf(xv, wB.x, a[8]);  a[9]  = fmaf(xv, wB.y, a[9]);
            a[10] = fmaf(xv, wB.z, a[10]); a[11] = fmaf(xv, wB.w, a[11]);
            a[12] = fmaf(xv, wC.x, a[12]); a[13] = fmaf(xv, wC.y, a[13]);
            a[14] = fmaf(xv, wC.z, a[14]); a[15] = fmaf(xv, wC.w, a[15]);
        }
#pragma unroll
        for (int t = 0; t < 16; t++) {
            float vv = fmaxf(a[t], 0.0f);
#pragma unroll
            for (int off = 16; off > 0; off >>= 1)
                vv = fmaxf(vv, __shfl_xor_sync(0xffffffffu, vv, off));
            a[t] = vv;
        }
        if (lane == 0) {
            float4* o4 = (float4*)&op[ch * 16];
            o4[0] = make_float4(a[0],  a[1],  a[2],  a[3]);
            o4[1] = make_float4(a[4],  a[5],  a[6],  a[7]);
            o4[2] = make_float4(a[8],  a[9],  a[10], a[11]);
            o4[3] = make_float4(a[12], a[13], a[14], a[15]);
        }
    }
}

// ---------------------------------------------------------------------------
extern "C" void kernel_launch(void* const* d_in, const int* in_sizes, int n_in,
                              void* d_out, int out_size)
{
    const float* xyzs  = (const float*)d_in[0];
    const float* feats = (const float*)d_in[1];
    const float* w1 = (const float*)d_in[2];
    const float* b1 = (const float*)d_in[3];
    const float* g1 = (const float*)d_in[4];
    const float* bt1= (const float*)d_in[5];
    const float* m1 = (const float*)d_in[6];
    const float* v1 = (const float*)d_in[7];
    const float* w2 = (const float*)d_in[8];
    const float* b2 = (const float*)d_in[9];
    const float* g2 = (const float*)d_in[10];
    const float* bt2= (const float*)d_in[11];
    const float* m2 = (const float*)d_in[12];
    const float* v2 = (const float*)d_in[13];
    const float* w3 = (const float*)d_in[14];
    const float* b3 = (const float*)d_in[15];
    const float* g3 = (const float*)d_in[16];
    const float* bt3= (const float*)d_in[17];
    const float* m3 = (const float*)d_in[18];
    const float* v3 = (const float*)d_in[19];

    float* outc = (float*)d_out;                      // [B,S,3]
    float* outf = outc + (size_t)B_ * S_ * 3;         // [B,S,128]

    const int FPS_SMEM  = 3 * N_ * sizeof(float);                 // 96 KB
    const int BALL_SMEM = N_ * sizeof(float4);                    // 128 KB
    const int MLP_SMEM  = (CIN_ * 64 + 64 * 64 + 64 * 128 + 64 + 64 + 128 + 256) * sizeof(float);

    cudaFuncSetAttribute(fps_kernel,  cudaFuncAttributeMaxDynamicSharedMemorySize, FPS_SMEM);
    cudaFuncSetAttribute(ball_kernel, cudaFuncAttributeMaxDynamicSharedMemorySize, BALL_SMEM);
    cudaFuncSetAttribute(mlp_kernel,  cudaFuncAttributeMaxDynamicSharedMemorySize, MLP_SMEM);

    fps_kernel <<<B_, 1024, FPS_SMEM>>>(xyzs, outc);
    ball_kernel<<<(B_ * S_) / 128, 128, BALL_SMEM>>>(xyzs, outc);
    mlp_kernel <<<(B_ * S_) / 4, 128, MLP_SMEM>>>(
        xyzs, feats,
        w1, b1, g1, bt1, m1, v1,
        w2, b2, g2, bt2, m2, v2,
        w3, b3, g3, bt3, m3, v3,
        outc, outf);
}

// round 4
// speedup vs baseline: 1.0329x; 1.0329x over previous
#include <cuda_runtime.h>
#include <cstdint>
#include <cstddef>

#define B_   8
#define N_   8192
#define S_   2048
#define K_   32
#define F_   64
#define CIN_ 67
#define EPSF 1e-5f

typedef unsigned long long ull;

// scratch: group indices (-1 padded), 2 MB static device array
__device__ int g_gidx[B_ * S_ * K_];

// ---- packed f32x2 helpers (per-lane IEEE rn, bit-identical to scalar) ----
__device__ __forceinline__ ull pk2(float lo, float hi) {
    ull r; asm("mov.b64 %0, {%1, %2};" : "=l"(r) : "f"(lo), "f"(hi)); return r;
}
__device__ __forceinline__ void upk2(ull v, float& lo, float& hi) {
    asm("mov.b64 {%0, %1}, %2;" : "=f"(lo), "=f"(hi) : "l"(v));
}
__device__ __forceinline__ ull add2(ull a, ull b) {
    ull r; asm("add.rn.f32x2 %0, %1, %2;" : "=l"(r) : "l"(a), "l"(b)); return r;
}
__device__ __forceinline__ ull mul2(ull a, ull b) {
    ull r; asm("mul.rn.f32x2 %0, %1, %2;" : "=l"(r) : "l"(a), "l"(b)); return r;
}
__device__ __forceinline__ ull fma2(ull a, ull b, ull c) {
    ull r; asm("fma.rn.f32x2 %0, %1, %2, %3;" : "=l"(r) : "l"(a), "l"(b), "l"(c)); return r;
}

// ---------------------------------------------------------------------------
// Kernel 1: farthest point sampling. One CTA per batch, 1024 threads,
// 8 points per thread (4 packed pairs). Distance math: per-lane rn ops in
// canonical order ((dx*dx + dy*dy) + dz*dz); f32x2 packing is bit-identical.
// ---------------------------------------------------------------------------
__global__ __launch_bounds__(1024, 1)
void fps_kernel(const float* __restrict__ xyzs, float* __restrict__ outc)
{
    extern __shared__ float sm1[];
    float* sx = sm1;
    float* sy = sm1 + N_;
    float* sz = sm1 + 2 * N_;
    __shared__ float swv[32];
    __shared__ int   swi[32];

    const int b    = blockIdx.x;
    const int tid  = threadIdx.x;
    const int lane = tid & 31;
    const int wid  = tid >> 5;
    const float* xyz = xyzs + (size_t)b * N_ * 3;

    // pair p: slots (tid + 2p*1024, tid + (2p+1)*1024), ascending index order
    ull px2[4], py2[4], pz2[4];
    float mind[8];
#pragma unroll
    for (int p = 0; p < 4; p++) {
        int i0 = tid + (2 * p) * 1024;
        int i1 = tid + (2 * p + 1) * 1024;
        float X0 = xyz[i0 * 3 + 0], Y0 = xyz[i0 * 3 + 1], Z0 = xyz[i0 * 3 + 2];
        float X1 = xyz[i1 * 3 + 0], Y1 = xyz[i1 * 3 + 1], Z1 = xyz[i1 * 3 + 2];
        px2[p] = pk2(X0, X1); py2[p] = pk2(Y0, Y1); pz2[p] = pk2(Z0, Z1);
        sx[i0] = X0; sy[i0] = Y0; sz[i0] = Z0;
        sx[i1] = X1; sy[i1] = Y1; sz[i1] = Z1;
        mind[2 * p] = 1e10f; mind[2 * p + 1] = 1e10f;
    }
    __syncthreads();

    float cx = sx[0], cy = sy[0], cz = sz[0];
    if (tid == 0) {
        float* o = outc + (size_t)b * S_ * 3;
        o[0] = cx; o[1] = cy; o[2] = cz;
    }

    for (int s = 1; s < S_; s++) {
        // negated center, duplicated in both halves: add(p, -c) == __fsub_rn(p, c)
        ull ncx2 = pk2(-cx, -cx), ncy2 = pk2(-cy, -cy), ncz2 = pk2(-cz, -cz);

        float bv = -1.0f;
        int   bi = 0;
#pragma unroll
        for (int p = 0; p < 4; p++) {
            ull dx2 = add2(px2[p], ncx2);
            ull dy2 = add2(py2[p], ncy2);
            ull dz2 = add2(pz2[p], ncz2);
            ull d2  = add2(add2(mul2(dx2, dx2), mul2(dy2, dy2)), mul2(dz2, dz2));
            float dlo, dhi; upk2(d2, dlo, dhi);
            float m0 = fminf(mind[2 * p],     dlo);
            float m1 = fminf(mind[2 * p + 1], dhi);
            mind[2 * p]     = m0;
            mind[2 * p + 1] = m1;
            if (m0 > bv) { bv = m0; bi = tid + (2 * p) * 1024; }
            if (m1 > bv) { bv = m1; bi = tid + (2 * p + 1) * 1024; }
        }
        // warp reduce (val, idx), tie -> lower idx
#pragma unroll
        for (int off = 16; off > 0; off >>= 1) {
            float ov = __shfl_down_sync(0xffffffffu, bv, off);
            int   oi = __shfl_down_sync(0xffffffffu, bi, off);
            if (ov > bv || (ov == bv && oi < bi)) { bv = ov; bi = oi; }
        }
        if (lane == 0) { swv[wid] = bv; swi[wid] = bi; }
        __syncthreads();

        // all warps redundantly reduce the 32 partials (xor butterfly ->
        // every lane converges to the global best). Removes warp0-only phase.
        float v = swv[lane];
        int   i2 = swi[lane];
#pragma unroll
        for (int off = 16; off > 0; off >>= 1) {
            float ov = __shfl_xor_sync(0xffffffffu, v, off);
            int   oi = __shfl_xor_sync(0xffffffffu, i2, off);
            if (ov > v || (ov == v && oi < i2)) { v = ov; i2 = oi; }
        }
        cx = sx[i2]; cy = sy[i2]; cz = sz[i2];
        if (tid == 0) {
            float* o = outc + ((size_t)b * S_ + s) * 3;
            o[0] = cx; o[1] = cy; o[2] = cz;
        }
        __syncthreads();   // protect swv/swi for next iteration
    }
}

// ---------------------------------------------------------------------------
// Kernel 2: ball query. Each thread owns one center; points broadcast from
// SMEM (float4: x,y,z,|x|^2). First-K-by-index semantics via sequential scan.
// d2 = (|c|^2 + |x|^2) - 2*((cx*px + cy*py) + cz*pz), uncontracted rn ops.
// ---------------------------------------------------------------------------
__global__ __launch_bounds__(128)
void ball_kernel(const float* __restrict__ xyzs, const float* __restrict__ centers)
{
    extern __shared__ float4 sp[];   // [N_] : 128 KB

    const int cbase = blockIdx.x * 128;
    const int b     = cbase >> 11;           // / 2048
    const float* xyz = xyzs + (size_t)b * N_ * 3;

    for (int i = threadIdx.x; i < N_; i += 128) {
        float X = xyz[i * 3 + 0];
        float Y = xyz[i * 3 + 1];
        float Z = xyz[i * 3 + 2];
        float nrm = __fadd_rn(__fadd_rn(__fmul_rn(X, X), __fmul_rn(Y, Y)),
                              __fmul_rn(Z, Z));
        sp[i] = make_float4(X, Y, Z, nrm);
    }
    __syncthreads();

    const int ci = cbase + threadIdx.x;
    const float* c = centers + (size_t)ci * 3;
    const float cx = c[0], cy = c[1], cz = c[2];
    const float cc = __fadd_rn(__fadd_rn(__fmul_rn(cx, cx), __fmul_rn(cy, cy)),
                               __fmul_rn(cz, cz));
    const float R2 = 0.2f * 0.2f;

    int cnt = 0;
    for (int n = 0; n < N_; n++) {
        float4 p = sp[n];
        float dot = __fadd_rn(__fadd_rn(__fmul_rn(cx, p.x), __fmul_rn(cy, p.y)),
                              __fmul_rn(cz, p.z));
        float d2  = __fsub_rn(__fadd_rn(cc, p.w), __fmul_rn(2.0f, dot));
        if (d2 <= R2 && cnt < K_) {
            g_gidx[(size_t)ci * K_ + cnt] = n;
            cnt++;
        }
        if ((n & 63) == 63 && __all_sync(0xffffffffu, cnt >= K_)) break;
    }
    for (int t = cnt; t < K_; t++) g_gidx[(size_t)ci * K_ + t] = -1;
}

// ---------------------------------------------------------------------------
// Kernel 3: gather + 3-layer MLP (BN folded) + max over K.
// 128 threads = 4 warps per block, one center per warp. lane = k slot.
// fma.rn.f32x2 pairs adjacent output channels (bit-identical to scalar fmaf).
// ---------------------------------------------------------------------------
template<int CI>
__device__ __forceinline__ void mlp_layer64(const float* __restrict__ x,
                                            const float* __restrict__ sW,
                                            const float* __restrict__ sB,
                                            float* __restrict__ y)
{
#pragma unroll
    for (int ch = 0; ch < 4; ch++) {
        ull acc[8];
#pragma unroll
        for (int t = 0; t < 8; t++)
            acc[t] = *(const ull*)(sB + ch * 16 + 2 * t);
#pragma unroll
        for (int c = 0; c < CI; c++) {
            ull xv2 = pk2(x[c], x[c]);
            const ulonglong2* wp = (const ulonglong2*)(sW + c * 64 + ch * 16);
            ulonglong2 w0 = wp[0], w1 = wp[1], w2 = wp[2], w3 = wp[3];
            acc[0] = fma2(xv2, w0.x, acc[0]); acc[1] = fma2(xv2, w0.y, acc[1]);
            acc[2] = fma2(xv2, w1.x, acc[2]); acc[3] = fma2(xv2, w1.y, acc[3]);
            acc[4] = fma2(xv2, w2.x, acc[4]); acc[5] = fma2(xv2, w2.y, acc[5]);
            acc[6] = fma2(xv2, w3.x, acc[6]); acc[7] = fma2(xv2, w3.y, acc[7]);
        }
#pragma unroll
        for (int t = 0; t < 8; t++) {
            float lo, hi; upk2(acc[t], lo, hi);
            y[ch * 16 + 2 * t]     = fmaxf(lo, 0.0f);
            y[ch * 16 + 2 * t + 1] = fmaxf(hi, 0.0f);
        }
    }
}

__global__ __launch_bounds__(128)
void mlp_kernel(const float* __restrict__ xyzs, const float* __restrict__ feats,
                const float* __restrict__ w1, const float* __restrict__ b1,
                const float* __restrict__ g1, const float* __restrict__ bt1,
                const float* __restrict__ m1, const float* __restrict__ v1,
                const float* __restrict__ w2, const float* __restrict__ b2,
                const float* __restrict__ g2, const float* __restrict__ bt2,
                const float* __restrict__ m2, const float* __restrict__ v2,
                const float* __restrict__ w3, const float* __restrict__ b3,
                const float* __restrict__ g3, const float* __restrict__ bt3,
                const float* __restrict__ m3, const float* __restrict__ v3,
                const float* __restrict__ centers, float* __restrict__ outf)
{
    extern __shared__ float sm3[];
    float* sW1 = sm3;                 // [67][64] transposed: sW1[c*64+o]
    float* sW2 = sW1 + CIN_ * 64;     // [64][64]
    float* sW3 = sW2 + 64 * 64;       // [64][128]
    float* sB1 = sW3 + 64 * 128;      // 64
    float* sB2 = sB1 + 64;            // 64
    float* sB3 = sB2 + 64;            // 128
    float* sS  = sB3 + 128;           // 256 scales: s1[64] s2[64] s3[128]

    const int tid = threadIdx.x;

    if (tid < 64) {
        float s = g1[tid] * rsqrtf(v1[tid] + EPSF);
        sS[tid] = s;
        sB1[tid] = (b1[tid] - m1[tid]) * s + bt1[tid];
    } else {
        int o = tid - 64;
        float s = g2[o] * rsqrtf(v2[o] + EPSF);
        sS[64 + o] = s;
        sB2[o] = (b2[o] - m2[o]) * s + bt2[o];
    }
    {
        float s = g3[tid] * rsqrtf(v3[tid] + EPSF);
        sS[128 + tid] = s;
        sB3[tid] = (b3[tid] - m3[tid]) * s + bt3[tid];
    }
    __syncthreads();

    for (int i = tid; i < CIN_ * 64; i += 128) {
        int c = i >> 6, o = i & 63;
        sW1[i] = w1[o * CIN_ + c] * sS[o];
    }
    for (int i = tid; i < 64 * 64; i += 128) {
        int c = i >> 6, o = i & 63;
        sW2[i] = w2[o * 64 + c] * sS[64 + o];
    }
    for (int i = tid; i < 64 * 128; i += 128) {
        int c = i >> 7, o = i & 127;
        sW3[i] = w3[o * 64 + c] * sS[128 + o];
    }
    __syncthreads();

    const int warp = tid >> 5;
    const int lane = tid & 31;
    const int ci   = blockIdx.x * 4 + warp;
    const int b    = ci >> 11;   // / 2048

    // gather input row for this lane's k slot
    const int ig = g_gidx[(size_t)ci * K_ + lane];
    float x[CIN_];
    if (ig >= 0) {
        const float* ctr = centers + (size_t)ci * 3;
        const float* p   = xyzs + ((size_t)b * N_ + ig) * 3;
        x[0] = p[0] - ctr[0];
        x[1] = p[1] - ctr[1];
        x[2] = p[2] - ctr[2];
        const float4* f4 = (const float4*)(feats + ((size_t)b * N_ + ig) * F_);
#pragma unroll
        for (int q = 0; q < 16; q++) {
            float4 t = f4[q];
            x[3 + 4 * q + 0] = t.x;
            x[3 + 4 * q + 1] = t.y;
            x[3 + 4 * q + 2] = t.z;
            x[3 + 4 * q + 3] = t.w;
        }
    } else {
#pragma unroll
        for (int q = 0; q < CIN_; q++) x[q] = 0.0f;
    }

    // layer 1: 67 -> 64, layer 2: 64 -> 64
    float y1[64];
    mlp_layer64<CIN_>(x, sW1, sB1, y1);
    float y2[64];
    mlp_layer64<64>(y1, sW2, sB2, y2);

    // layer 3: 64 -> 128, relu, warp max over K, store
    float* op = outf + (size_t)ci * 128;
#pragma unroll
    for (int ch = 0; ch < 8; ch++) {
        ull acc[8];
#pragma unroll
        for (int t = 0; t < 8; t++)
            acc[t] = *(const ull*)(sB3 + ch * 16 + 2 * t);
#pragma unroll
        for (int c = 0; c < 64; c++) {
            ull xv2 = pk2(y2[c], y2[c]);
            const ulonglong2* wp = (const ulonglong2*)(sW3 + c * 128 + ch * 16);
            ulonglong2 w0 = wp[0], w1 = wp[1], w2 = wp[2], w3 = wp[3];
            acc[0] = fma2(xv2, w0.x, acc[0]); acc[1] = fma2(xv2, w0.y, acc[1]);
            acc[2] = fma2(xv2, w1.x, acc[2]); acc[3] = fma2(xv2, w1.y, acc[3]);
            acc[4] = fma2(xv2, w2.x, acc[4]); acc[5] = fma2(xv2, w2.y, acc[5]);
            acc[6] = fma2(xv2, w3.x, acc[6]); acc[7] = fma2(xv2, w3.y, acc[7]);
        }
        float a[16];
#pragma unroll
        for (int t = 0; t < 8; t++) {
            float lo, hi; upk2(acc[t], lo, hi);
            a[2 * t]     = fmaxf(lo, 0.0f);
            a[2 * t + 1] = fmaxf(hi, 0.0f);
        }
#pragma unroll
        for (int t = 0; t < 16; t++) {
            float vv = a[t];
#pragma unroll
            for (int off = 16; off > 0; off >>= 1)
                vv = fmaxf(vv, __shfl_xor_sync(0xffffffffu, vv, off));
            a[t] = vv;
        }
        if (lane == 0) {
            float4* o4 = (float4*)&op[ch * 16];
            o4[0] = make_float4(a[0],  a[1],  a[2],  a[3]);
            o4[1] = make_float4(a[4],  a[5],  a[6],  a[7]);
            o4[2] = make_float4(a[8],  a[9],  a[10], a[11]);
            o4[3] = make_float4(a[12], a[13], a[14], a[15]);
        }
    }
}

// ---------------------------------------------------------------------------
extern "C" void kernel_launch(void* const* d_in, const int* in_sizes, int n_in,
                              void* d_out, int out_size)
{
    const float* xyzs  = (const float*)d_in[0];
    const float* feats = (const float*)d_in[1];
    const float* w1 = (const float*)d_in[2];
    const float* b1 = (const float*)d_in[3];
    const float* g1 = (const float*)d_in[4];
    const float* bt1= (const float*)d_in[5];
    const float* m1 = (const float*)d_in[6];
    const float* v1 = (const float*)d_in[7];
    const float* w2 = (const float*)d_in[8];
    const float* b2 = (const float*)d_in[9];
    const float* g2 = (const float*)d_in[10];
    const float* bt2= (const float*)d_in[11];
    const float* m2 = (const float*)d_in[12];
    const float* v2 = (const float*)d_in[13];
    const float* w3 = (const float*)d_in[14];
    const float* b3 = (const float*)d_in[15];
    const float* g3 = (const float*)d_in[16];
    const float* bt3= (const float*)d_in[17];
    const float* m3 = (const float*)d_in[18];
    const float* v3 = (const float*)d_in[19];

    float* outc = (float*)d_out;                      // [B,S,3]
    float* outf = outc + (size_t)B_ * S_ * 3;         // [B,S,128]

    const int FPS_SMEM  = 3 * N_ * sizeof(float);                 // 96 KB
    const int BALL_SMEM = N_ * sizeof(float4);                    // 128 KB
    const int MLP_SMEM  = (CIN_ * 64 + 64 * 64 + 64 * 128 + 64 + 64 + 128 + 256) * sizeof(float);

    cudaFuncSetAttribute(fps_kernel,  cudaFuncAttributeMaxDynamicSharedMemorySize, FPS_SMEM);
    cudaFuncSetAttribute(ball_kernel, cudaFuncAttributeMaxDynamicSharedMemorySize, BALL_SMEM);
    cudaFuncSetAttribute(mlp_kernel,  cudaFuncAttributeMaxDynamicSharedMemorySize, MLP_SMEM);

    fps_kernel <<<B_, 1024, FPS_SMEM>>>(xyzs, outc);
    ball_kernel<<<(B_ * S_) / 128, 128, BALL_SMEM>>>(xyzs, outc);
    mlp_kernel <<<(B_ * S_) / 4, 128, MLP_SMEM>>>(
        xyzs, feats,
        w1, b1, g1, bt1, m1, v1,
        w2, b2, g2, bt2, m2, v2,
        w3, b3, g3, bt3, m3, v3,
        outc, outf);
}

// round 5
// speedup vs baseline: 1.5625x; 1.5127x over previous
#include <cuda_runtime.h>
#include <cstdint>
#include <cstddef>

#define B_   8
#define N_   8192
#define S_   2048
#define K_   32
#define F_   64
#define CIN_ 67
#define EPSF 1e-5f

typedef unsigned long long ull;

// scratch: group indices (-1 padded), 2 MB static device array
__device__ int g_gidx[B_ * S_ * K_];

// ---- packed f32x2 helpers (per-lane IEEE rn, bit-identical to scalar) ----
__device__ __forceinline__ ull pk2(float lo, float hi) {
    ull r; asm("mov.b64 %0, {%1, %2};" : "=l"(r) : "f"(lo), "f"(hi)); return r;
}
__device__ __forceinline__ void upk2(ull v, float& lo, float& hi) {
    asm("mov.b64 {%0, %1}, %2;" : "=f"(lo), "=f"(hi) : "l"(v));
}
__device__ __forceinline__ ull add2(ull a, ull b) {
    ull r; asm("add.rn.f32x2 %0, %1, %2;" : "=l"(r) : "l"(a), "l"(b)); return r;
}
__device__ __forceinline__ ull mul2(ull a, ull b) {
    ull r; asm("mul.rn.f32x2 %0, %1, %2;" : "=l"(r) : "l"(a), "l"(b)); return r;
}
__device__ __forceinline__ ull fma2(ull a, ull b, ull c) {
    ull r; asm("fma.rn.f32x2 %0, %1, %2, %3;" : "=l"(r) : "l"(a), "l"(b), "l"(c)); return r;
}

// ---------------------------------------------------------------------------
// Kernel 1: farthest point sampling. One CTA per batch, 1024 threads,
// 8 points per thread (4 packed pairs). Distance math: per-lane rn ops in
// canonical order ((dx*dx + dy*dy) + dz*dz); f32x2 packing is bit-identical.
// Argmax: value phase via redux.sync.max.u32 on float bits (distances >= 0,
// so unsigned order == float order), then index-recovery phase via
// redux.sync.min.u32 over global indices (lowest index on ties == jnp.argmax).
// ---------------------------------------------------------------------------
__global__ __launch_bounds__(1024, 1)
void fps_kernel(const float* __restrict__ xyzs, float* __restrict__ outc)
{
    extern __shared__ float sm1[];
    float* sx = sm1;
    float* sy = sm1 + N_;
    float* sz = sm1 + 2 * N_;
    __shared__ unsigned swv[32];
    __shared__ unsigned swi[32];

    const int b    = blockIdx.x;
    const int tid  = threadIdx.x;
    const int lane = tid & 31;
    const int wid  = tid >> 5;
    const float* xyz = xyzs + (size_t)b * N_ * 3;

    // pair p: slots (tid + 2p*1024, tid + (2p+1)*1024), ascending index order
    ull px2[4], py2[4], pz2[4];
    float mind[8];
#pragma unroll
    for (int p = 0; p < 4; p++) {
        int i0 = tid + (2 * p) * 1024;
        int i1 = tid + (2 * p + 1) * 1024;
        float X0 = xyz[i0 * 3 + 0], Y0 = xyz[i0 * 3 + 1], Z0 = xyz[i0 * 3 + 2];
        float X1 = xyz[i1 * 3 + 0], Y1 = xyz[i1 * 3 + 1], Z1 = xyz[i1 * 3 + 2];
        px2[p] = pk2(X0, X1); py2[p] = pk2(Y0, Y1); pz2[p] = pk2(Z0, Z1);
        sx[i0] = X0; sy[i0] = Y0; sz[i0] = Z0;
        sx[i1] = X1; sy[i1] = Y1; sz[i1] = Z1;
        mind[2 * p] = 1e10f; mind[2 * p + 1] = 1e10f;
    }
    __syncthreads();

    float cx = sx[0], cy = sy[0], cz = sz[0];
    if (tid == 0) {
        float* o = outc + (size_t)b * S_ * 3;
        o[0] = cx; o[1] = cy; o[2] = cz;
    }

    for (int s = 1; s < S_; s++) {
        // negated center, duplicated in both halves: add(p, -c) == __fsub_rn(p, c)
        ull ncx2 = pk2(-cx, -cx), ncy2 = pk2(-cy, -cy), ncz2 = pk2(-cz, -cz);

        // ---- value phase: update mind, track running max (no index) ----
        float bv = -1.0f;
#pragma unroll
        for (int p = 0; p < 4; p++) {
            ull dx2 = add2(px2[p], ncx2);
            ull dy2 = add2(py2[p], ncy2);
            ull dz2 = add2(pz2[p], ncz2);
            ull d2  = add2(add2(mul2(dx2, dx2), mul2(dy2, dy2)), mul2(dz2, dz2));
            float dlo, dhi; upk2(d2, dlo, dhi);
            float m0 = fminf(mind[2 * p],     dlo);
            float m1 = fminf(mind[2 * p + 1], dhi);
            mind[2 * p]     = m0;
            mind[2 * p + 1] = m1;
            bv = fmaxf(bv, fmaxf(m0, m1));
        }
        // distances >= 0 -> float order == unsigned bit order
        unsigned wmax = __reduce_max_sync(0xffffffffu, __float_as_uint(bv));
        if (lane == 0) swv[wid] = wmax;
        __syncthreads();
        unsigned gmax = __reduce_max_sync(0xffffffffu, swv[lane]);
        float gbv = __uint_as_float(gmax);

        // ---- index phase: only warps holding the max scan for it ----
        unsigned cand = 0xffffffffu;
        if (wmax == gmax) {   // warp-uniform branch
#pragma unroll
            for (int j = 7; j >= 0; j--)
                if (mind[j] == gbv) cand = (unsigned)(tid + j * 1024);
            cand = __reduce_min_sync(0xffffffffu, cand);
        }
        if (lane == 0) swi[wid] = cand;
        __syncthreads();
        unsigned gidx = __reduce_min_sync(0xffffffffu, swi[lane]);

        cx = sx[gidx]; cy = sy[gidx]; cz = sz[gidx];
        if (tid == 0) {
            float* o = outc + ((size_t)b * S_ + s) * 3;
            o[0] = cx; o[1] = cy; o[2] = cz;
        }
    }
}

// ---------------------------------------------------------------------------
// Kernel 2: ball query. Each thread owns one center; points broadcast from
// SMEM (float4: x,y,z,|x|^2). First-K-by-index semantics via sequential scan.
// d2 = (|c|^2 + |x|^2) - 2*((cx*px + cy*py) + cz*pz), uncontracted rn ops.
// ---------------------------------------------------------------------------
__global__ __launch_bounds__(128)
void ball_kernel(const float* __restrict__ xyzs, const float* __restrict__ centers)
{
    extern __shared__ float4 sp[];   // [N_] : 128 KB

    const int cbase = blockIdx.x * 128;
    const int b     = cbase >> 11;           // / 2048
    const float* xyz = xyzs + (size_t)b * N_ * 3;

    for (int i = threadIdx.x; i < N_; i += 128) {
        float X = xyz[i * 3 + 0];
        float Y = xyz[i * 3 + 1];
        float Z = xyz[i * 3 + 2];
        float nrm = __fadd_rn(__fadd_rn(__fmul_rn(X, X), __fmul_rn(Y, Y)),
                              __fmul_rn(Z, Z));
        sp[i] = make_float4(X, Y, Z, nrm);
    }
    __syncthreads();

    const int ci = cbase + threadIdx.x;
    const float* c = centers + (size_t)ci * 3;
    const float cx = c[0], cy = c[1], cz = c[2];
    const float cc = __fadd_rn(__fadd_rn(__fmul_rn(cx, cx), __fmul_rn(cy, cy)),
                               __fmul_rn(cz, cz));
    const float R2 = 0.2f * 0.2f;

    int cnt = 0;
    for (int n = 0; n < N_; n++) {
        float4 p = sp[n];
        float dot = __fadd_rn(__fadd_rn(__fmul_rn(cx, p.x), __fmul_rn(cy, p.y)),
                              __fmul_rn(cz, p.z));
        float d2  = __fsub_rn(__fadd_rn(cc, p.w), __fmul_rn(2.0f, dot));
        if (d2 <= R2 && cnt < K_) {
            g_gidx[(size_t)ci * K_ + cnt] = n;
            cnt++;
        }
        if ((n & 63) == 63 && __all_sync(0xffffffffu, cnt >= K_)) break;
    }
    for (int t = cnt; t < K_; t++) g_gidx[(size_t)ci * K_ + t] = -1;
}

// ---------------------------------------------------------------------------
// Kernel 3: gather + 3-layer MLP (BN folded) + max over K.
// 128 threads = 4 warps per block, one center per warp. lane = k slot.
// fma.rn.f32x2 pairs adjacent output channels (bit-identical to scalar fmaf).
// Max-pool over K via redux.sync.max.u32 on relu outputs (>= 0; mask bit 31
// to canonicalize a possible -0.0).
// ---------------------------------------------------------------------------
template<int CI>
__device__ __forceinline__ void mlp_layer64(const float* __restrict__ x,
                                            const float* __restrict__ sW,
                                            const float* __restrict__ sB,
                                            float* __restrict__ y)
{
#pragma unroll
    for (int ch = 0; ch < 4; ch++) {
        ull acc[8];
#pragma unroll
        for (int t = 0; t < 8; t++)
            acc[t] = *(const ull*)(sB + ch * 16 + 2 * t);
#pragma unroll
        for (int c = 0; c < CI; c++) {
            ull xv2 = pk2(x[c], x[c]);
            const ulonglong2* wp = (const ulonglong2*)(sW + c * 64 + ch * 16);
            ulonglong2 w0 = wp[0], w1 = wp[1], w2 = wp[2], w3 = wp[3];
            acc[0] = fma2(xv2, w0.x, acc[0]); acc[1] = fma2(xv2, w0.y, acc[1]);
            acc[2] = fma2(xv2, w1.x, acc[2]); acc[3] = fma2(xv2, w1.y, acc[3]);
            acc[4] = fma2(xv2, w2.x, acc[4]); acc[5] = fma2(xv2, w2.y, acc[5]);
            acc[6] = fma2(xv2, w3.x, acc[6]); acc[7] = fma2(xv2, w3.y, acc[7]);
        }
#pragma unroll
        for (int t = 0; t < 8; t++) {
            float lo, hi; upk2(acc[t], lo, hi);
            y[ch * 16 + 2 * t]     = fmaxf(lo, 0.0f);
            y[ch * 16 + 2 * t + 1] = fmaxf(hi, 0.0f);
        }
    }
}

__global__ __launch_bounds__(128)
void mlp_kernel(const float* __restrict__ xyzs, const float* __restrict__ feats,
                const float* __restrict__ w1, const float* __restrict__ b1,
                const float* __restrict__ g1, const float* __restrict__ bt1,
                const float* __restrict__ m1, const float* __restrict__ v1,
                const float* __restrict__ w2, const float* __restrict__ b2,
                const float* __restrict__ g2, const float* __restrict__ bt2,
                const float* __restrict__ m2, const float* __restrict__ v2,
                const float* __restrict__ w3, const float* __restrict__ b3,
                const float* __restrict__ g3, const float* __restrict__ bt3,
                const float* __restrict__ m3, const float* __restrict__ v3,
                const float* __restrict__ centers, float* __restrict__ outf)
{
    extern __shared__ float sm3[];
    float* sW1 = sm3;                 // [67][64] transposed: sW1[c*64+o]
    float* sW2 = sW1 + CIN_ * 64;     // [64][64]
    float* sW3 = sW2 + 64 * 64;       // [64][128]
    float* sB1 = sW3 + 64 * 128;      // 64
    float* sB2 = sB1 + 64;            // 64
    float* sB3 = sB2 + 64;            // 128
    float* sS  = sB3 + 128;           // 256 scales: s1[64] s2[64] s3[128]

    const int tid = threadIdx.x;

    if (tid < 64) {
        float s = g1[tid] * rsqrtf(v1[tid] + EPSF);
        sS[tid] = s;
        sB1[tid] = (b1[tid] - m1[tid]) * s + bt1[tid];
    } else {
        int o = tid - 64;
        float s = g2[o] * rsqrtf(v2[o] + EPSF);
        sS[64 + o] = s;
        sB2[o] = (b2[o] - m2[o]) * s + bt2[o];
    }
    {
        float s = g3[tid] * rsqrtf(v3[tid] + EPSF);
        sS[128 + tid] = s;
        sB3[tid] = (b3[tid] - m3[tid]) * s + bt3[tid];
    }
    __syncthreads();

    for (int i = tid; i < CIN_ * 64; i += 128) {
        int c = i >> 6, o = i & 63;
        sW1[i] = w1[o * CIN_ + c] * sS[o];
    }
    for (int i = tid; i < 64 * 64; i += 128) {
        int c = i >> 6, o = i & 63;
        sW2[i] = w2[o * 64 + c] * sS[64 + o];
    }
    for (int i = tid; i < 64 * 128; i += 128) {
        int c = i >> 7, o = i & 127;
        sW3[i] = w3[o * 64 + c] * sS[128 + o];
    }
    __syncthreads();

    const int warp = tid >> 5;
    const int lane = tid & 31;
    const int ci   = blockIdx.x * 4 + warp;
    const int b    = ci >> 11;   // / 2048

    // gather input row for this lane's k slot
    const int ig = g_gidx[(size_t)ci * K_ + lane];
    float x[CIN_];
    if (ig >= 0) {
        const float* ctr = centers + (size_t)ci * 3;
        const float* p   = xyzs + ((size_t)b * N_ + ig) * 3;
        x[0] = p[0] - ctr[0];
        x[1] = p[1] - ctr[1];
        x[2] = p[2] - ctr[2];
        const float4* f4 = (const float4*)(feats + ((size_t)b * N_ + ig) * F_);
#pragma unroll
        for (int q = 0; q < 16; q++) {
            float4 t = f4[q];
            x[3 + 4 * q + 0] = t.x;
            x[3 + 4 * q + 1] = t.y;
            x[3 + 4 * q + 2] = t.z;
            x[3 + 4 * q + 3] = t.w;
        }
    } else {
#pragma unroll
        for (int q = 0; q < CIN_; q++) x[q] = 0.0f;
    }

    // layer 1: 67 -> 64, layer 2: 64 -> 64
    float y1[64];
    mlp_layer64<CIN_>(x, sW1, sB1, y1);
    float y2[64];
    mlp_layer64<64>(y1, sW2, sB2, y2);

    // layer 3: 64 -> 128, relu, warp max over K via redux, store
    float* op = outf + (size_t)ci * 128;
#pragma unroll
    for (int ch = 0; ch < 8; ch++) {
        ull acc[8];
#pragma unroll
        for (int t = 0; t < 8; t++)
            acc[t] = *(const ull*)(sB3 + ch * 16 + 2 * t);
#pragma unroll
        for (int c = 0; c < 64; c++) {
            ull xv2 = pk2(y2[c], y2[c]);
            const ulonglong2* wp = (const ulonglong2*)(sW3 + c * 128 + ch * 16);
            ulonglong2 w0 = wp[0], w1 = wp[1], w2 = wp[2], w3 = wp[3];
            acc[0] = fma2(xv2, w0.x, acc[0]); acc[1] = fma2(xv2, w0.y, acc[1]);
            acc[2] = fma2(xv2, w1.x, acc[2]); acc[3] = fma2(xv2, w1.y, acc[3]);
            acc[4] = fma2(xv2, w2.x, acc[4]); acc[5] = fma2(xv2, w2.y, acc[5]);
            acc[6] = fma2(xv2, w3.x, acc[6]); acc[7] = fma2(xv2, w3.y, acc[7]);
        }
        float a[16];
#pragma unroll
        for (int t = 0; t < 8; t++) {
            float lo, hi; upk2(acc[t], lo, hi);
            a[2 * t]     = fmaxf(lo, 0.0f);
            a[2 * t + 1] = fmaxf(hi, 0.0f);
        }
        // relu outputs >= 0 -> unsigned-bit max == float max (mask clears -0.0)
#pragma unroll
        for (int t = 0; t < 16; t++) {
            unsigned u = __float_as_uint(a[t]) & 0x7fffffffu;
            a[t] = __uint_as_float(__reduce_max_sync(0xffffffffu, u));
        }
        if (lane == 0) {
            float4* o4 = (float4*)&op[ch * 16];
            o4[0] = make_float4(a[0],  a[1],  a[2],  a[3]);
            o4[1] = make_float4(a[4],  a[5],  a[6],  a[7]);
            o4[2] = make_float4(a[8],  a[9],  a[10], a[11]);
            o4[3] = make_float4(a[12], a[13], a[14], a[15]);
        }
    }
}

// ---------------------------------------------------------------------------
extern "C" void kernel_launch(void* const* d_in, const int* in_sizes, int n_in,
                              void* d_out, int out_size)
{
    const float* xyzs  = (const float*)d_in[0];
    const float* feats = (const float*)d_in[1];
    const float* w1 = (const float*)d_in[2];
    const float* b1 = (const float*)d_in[3];
    const float* g1 = (const float*)d_in[4];
    const float* bt1= (const float*)d_in[5];
    const float* m1 = (const float*)d_in[6];
    const float* v1 = (const float*)d_in[7];
    const float* w2 = (const float*)d_in[8];
    const float* b2 = (const float*)d_in[9];
    const float* g2 = (const float*)d_in[10];
    const float* bt2= (const float*)d_in[11];
    const float* m2 = (const float*)d_in[12];
    const float* v2 = (const float*)d_in[13];
    const float* w3 = (const float*)d_in[14];
    const float* b3 = (const float*)d_in[15];
    const float* g3 = (const float*)d_in[16];
    const float* bt3= (const float*)d_in[17];
    const float* m3 = (const float*)d_in[18];
    const float* v3 = (const float*)d_in[19];

    float* outc = (float*)d_out;                      // [B,S,3]
    float* outf = outc + (size_t)B_ * S_ * 3;         // [B,S,128]

    const int FPS_SMEM  = 3 * N_ * sizeof(float);                 // 96 KB
    const int BALL_SMEM = N_ * sizeof(float4);                    // 128 KB
    const int MLP_SMEM  = (CIN_ * 64 + 64 * 64 + 64 * 128 + 64 + 64 + 128 + 256) * sizeof(float);

    cudaFuncSetAttribute(fps_kernel,  cudaFuncAttributeMaxDynamicSharedMemorySize, FPS_SMEM);
    cudaFuncSetAttribute(ball_kernel, cudaFuncAttributeMaxDynamicSharedMemorySize, BALL_SMEM);
    cudaFuncSetAttribute(mlp_kernel,  cudaFuncAttributeMaxDynamicSharedMemorySize, MLP_SMEM);

    fps_kernel <<<B_, 1024, FPS_SMEM>>>(xyzs, outc);
    ball_kernel<<<(B_ * S_) / 128, 128, BALL_SMEM>>>(xyzs, outc);
    mlp_kernel <<<(B_ * S_) / 4, 128, MLP_SMEM>>>(
        xyzs, feats,
        w1, b1, g1, bt1, m1, v1,
        w2, b2, g2, bt2, m2, v2,
        w3, b3, g3, bt3, m3, v3,
        outc, outf);
}

// round 6
// speedup vs baseline: 1.9538x; 1.2504x over previous
#include <cuda_runtime.h>
#include <cstdint>
#include <cstddef>

#define B_   8
#define N_   8192
#define S_   2048
#define K_   32
#define F_   64
#define CIN_ 67
#define EPSF 1e-5f

typedef unsigned long long ull;

// scratch: group indices (-1 padded), 2 MB static device array
__device__ int g_gidx[B_ * S_ * K_];

// ---- packed f32x2 helpers (per-lane IEEE rn, bit-identical to scalar) ----
__device__ __forceinline__ ull pk2(float lo, float hi) {
    ull r; asm("mov.b64 %0, {%1, %2};" : "=l"(r) : "f"(lo), "f"(hi)); return r;
}
__device__ __forceinline__ void upk2(ull v, float& lo, float& hi) {
    asm("mov.b64 {%0, %1}, %2;" : "=f"(lo), "=f"(hi) : "l"(v));
}
__device__ __forceinline__ ull add2(ull a, ull b) {
    ull r; asm("add.rn.f32x2 %0, %1, %2;" : "=l"(r) : "l"(a), "l"(b)); return r;
}
__device__ __forceinline__ ull mul2(ull a, ull b) {
    ull r; asm("mul.rn.f32x2 %0, %1, %2;" : "=l"(r) : "l"(a), "l"(b)); return r;
}
__device__ __forceinline__ ull fma2(ull a, ull b, ull c) {
    ull r; asm("fma.rn.f32x2 %0, %1, %2, %3;" : "=l"(r) : "l"(a), "l"(b), "l"(c)); return r;
}

// ---------------------------------------------------------------------------
// Kernel 1: farthest point sampling. One CTA per batch, 1024 threads,
// 8 points per thread (4 packed pairs). ONE barrier per step: per-warp
// (dist,idx) packed into 64-bit smem word (double-buffered by parity),
// cross-warp reduce via redux.max(hi) + redux.min(masked lo).
// Distance: per-lane rn ops in canonical order ((dx*dx+dy*dy)+dz*dz).
// ---------------------------------------------------------------------------
__global__ __launch_bounds__(1024, 1)
void fps_kernel(const float* __restrict__ xyzs, float* __restrict__ outc)
{
    extern __shared__ float sm1[];
    float* sx = sm1;
    float* sy = sm1 + N_;
    float* sz = sm1 + 2 * N_;
    __shared__ ull swp[2][32];

    const int b    = blockIdx.x;
    const int tid  = threadIdx.x;
    const int lane = tid & 31;
    const int wid  = tid >> 5;
    const float* xyz = xyzs + (size_t)b * N_ * 3;

    ull px2[4], py2[4], pz2[4];
    float mind[8];
#pragma unroll
    for (int p = 0; p < 4; p++) {
        int i0 = tid + (2 * p) * 1024;
        int i1 = tid + (2 * p + 1) * 1024;
        float X0 = xyz[i0 * 3 + 0], Y0 = xyz[i0 * 3 + 1], Z0 = xyz[i0 * 3 + 2];
        float X1 = xyz[i1 * 3 + 0], Y1 = xyz[i1 * 3 + 1], Z1 = xyz[i1 * 3 + 2];
        px2[p] = pk2(X0, X1); py2[p] = pk2(Y0, Y1); pz2[p] = pk2(Z0, Z1);
        sx[i0] = X0; sy[i0] = Y0; sz[i0] = Z0;
        sx[i1] = X1; sy[i1] = Y1; sz[i1] = Z1;
        mind[2 * p] = 1e10f; mind[2 * p + 1] = 1e10f;
    }
    __syncthreads();

    float cx = sx[0], cy = sy[0], cz = sz[0];
    if (tid == 0) {
        float* o = outc + (size_t)b * S_ * 3;
        o[0] = cx; o[1] = cy; o[2] = cz;
    }

    for (int s = 1; s < S_; s++) {
        ull ncx2 = pk2(-cx, -cx), ncy2 = pk2(-cy, -cy), ncz2 = pk2(-cz, -cz);

        float bv = -1.0f;
#pragma unroll
        for (int p = 0; p < 4; p++) {
            ull dx2 = add2(px2[p], ncx2);
            ull dy2 = add2(py2[p], ncy2);
            ull dz2 = add2(pz2[p], ncz2);
            ull d2  = add2(add2(mul2(dx2, dx2), mul2(dy2, dy2)), mul2(dz2, dz2));
            float dlo, dhi; upk2(d2, dlo, dhi);
            float m0 = fminf(mind[2 * p],     dlo);
            float m1 = fminf(mind[2 * p + 1], dhi);
            mind[2 * p]     = m0;
            mind[2 * p + 1] = m1;
            bv = fmaxf(bv, fmaxf(m0, m1));
        }
        // distances >= 0 -> float order == unsigned bit order
        unsigned wmax  = __reduce_max_sync(0xffffffffu, __float_as_uint(bv));
        float    wmaxf = __uint_as_float(wmax);
        unsigned cand  = 0xffffffffu;
#pragma unroll
        for (int j = 7; j >= 0; j--)
            if (mind[j] == wmaxf) cand = (unsigned)(tid + j * 1024);
        cand = __reduce_min_sync(0xffffffffu, cand);
        if (lane == 0) swp[s & 1][wid] = ((ull)wmax << 32) | (ull)cand;
        __syncthreads();

        ull key = swp[s & 1][lane];
        unsigned hi = (unsigned)(key >> 32), lo = (unsigned)key;
        unsigned ghi  = __reduce_max_sync(0xffffffffu, hi);
        unsigned gidx = __reduce_min_sync(0xffffffffu, (hi == ghi) ? lo : 0xffffffffu);

        cx = sx[gidx]; cy = sy[gidx]; cz = sz[gidx];
        if (tid == 0) {
            float* o = outc + ((size_t)b * S_ + s) * 3;
            o[0] = cx; o[1] = cy; o[2] = cz;
        }
    }
}

// ---------------------------------------------------------------------------
// Kernel 2: ball query, warp-per-center ballot scan. 32 lanes test 32 points
// per step; hits written in ascending point-index order via prefix popc ->
// exact first-K-by-index semantics. Same uncontracted rn distance ops.
// Block = 512 threads = 16 warps = 16 centers; grid = 16384/16 = 1024.
// ---------------------------------------------------------------------------
__global__ __launch_bounds__(512)
void ball_kernel(const float* __restrict__ xyzs, const float* __restrict__ centers)
{
    extern __shared__ float4 sp[];   // [N_] : 128 KB

    const int cbase = blockIdx.x * 16;
    const int b     = cbase >> 11;           // / 2048 (16 | 2048, no cross-batch)
    const float* xyz = xyzs + (size_t)b * N_ * 3;

    for (int i = threadIdx.x; i < N_; i += 512) {
        float X = xyz[i * 3 + 0];
        float Y = xyz[i * 3 + 1];
        float Z = xyz[i * 3 + 2];
        float nrm = __fadd_rn(__fadd_rn(__fmul_rn(X, X), __fmul_rn(Y, Y)),
                              __fmul_rn(Z, Z));
        sp[i] = make_float4(X, Y, Z, nrm);
    }
    __syncthreads();

    const int warp = threadIdx.x >> 5;
    const int lane = threadIdx.x & 31;
    const int ci   = cbase + warp;
    const float* c = centers + (size_t)ci * 3;
    const float cx = c[0], cy = c[1], cz = c[2];
    const float cc = __fadd_rn(__fadd_rn(__fmul_rn(cx, cx), __fmul_rn(cy, cy)),
                               __fmul_rn(cz, cz));
    const float R2 = 0.2f * 0.2f;
    const unsigned below = (1u << lane) - 1u;

    int cnt = 0;
    for (int chunk = 0; chunk < N_ / 32; chunk++) {
        int n = chunk * 32 + lane;
        float4 p = sp[n];
        float dot = __fadd_rn(__fadd_rn(__fmul_rn(cx, p.x), __fmul_rn(cy, p.y)),
                              __fmul_rn(cz, p.z));
        float d2  = __fsub_rn(__fadd_rn(cc, p.w), __fmul_rn(2.0f, dot));
        bool hit = (d2 <= R2);
        unsigned m = __ballot_sync(0xffffffffu, hit);
        int pos = cnt + __popc(m & below);
        if (hit && pos < K_) g_gidx[(size_t)ci * K_ + pos] = n;
        cnt += __popc(m);
        if (cnt >= K_) break;
    }
    for (int t = cnt + lane; t < K_; t += 32) g_gidx[(size_t)ci * K_ + t] = -1;
}

// ---------------------------------------------------------------------------
// Kernel 3: gather + 3-layer MLP (BN folded) + max over K.
// 4 warps/block, 4 centers per warp (grid 1024), lane = k slot.
// Activations staged in padded SMEM (per-lane rows, conflict-free strides);
// only the 32 ull accumulators live in registers -> no spills, small code.
// FMA order per output channel identical to previous rounds (bit-exact).
// ---------------------------------------------------------------------------
#define WPB 4
#define CPW 4
#define XS  69   // x row stride (67 used), gcd-free vs 32 banks
#define YS  65   // y row stride (64 used)

__device__ __forceinline__ void step64(ull* __restrict__ acc, float xv,
                                       const float* __restrict__ wrow)
{
    ull xv2 = pk2(xv, xv);
    const ulonglong2* wp = (const ulonglong2*)wrow;
#pragma unroll
    for (int t = 0; t < 16; t++) {
        ulonglong2 w = wp[t];
        acc[2 * t]     = fma2(xv2, w.x, acc[2 * t]);
        acc[2 * t + 1] = fma2(xv2, w.y, acc[2 * t + 1]);
    }
}

__global__ __launch_bounds__(128, 1)
void mlp_kernel(const float* __restrict__ xyzs, const float* __restrict__ feats,
                const float* __restrict__ w1, const float* __restrict__ b1,
                const float* __restrict__ g1, const float* __restrict__ bt1,
                const float* __restrict__ m1, const float* __restrict__ v1,
                const float* __restrict__ w2, const float* __restrict__ b2,
                const float* __restrict__ g2, const float* __restrict__ bt2,
                const float* __restrict__ m2, const float* __restrict__ v2,
                const float* __restrict__ w3, const float* __restrict__ b3,
                const float* __restrict__ g3, const float* __restrict__ bt3,
                const float* __restrict__ m3, const float* __restrict__ v3,
                const float* __restrict__ centers, float* __restrict__ outf)
{
    extern __shared__ float sm3[];
    float* sW1 = sm3;                 // [67][64] transposed: sW1[c*64+o]
    float* sW2 = sW1 + CIN_ * 64;     // [64][64]
    float* sW3 = sW2 + 64 * 64;       // [64][128]
    float* sB1 = sW3 + 64 * 128;      // 64
    float* sB2 = sB1 + 64;            // 64
    float* sB3 = sB2 + 64;            // 128
    float* sS  = sB3 + 128;           // 256 scales
    float* sX  = sS + 256;            // [128 threads][XS] staged x
    float* sY  = sX + 128 * XS;       // [128 threads][YS] staged y

    const int tid = threadIdx.x;

    if (tid < 64) {
        float s = g1[tid] * rsqrtf(v1[tid] + EPSF);
        sS[tid] = s;
        sB1[tid] = (b1[tid] - m1[tid]) * s + bt1[tid];
    } else {
        int o = tid - 64;
        float s = g2[o] * rsqrtf(v2[o] + EPSF);
        sS[64 + o] = s;
        sB2[o] = (b2[o] - m2[o]) * s + bt2[o];
    }
    {
        float s = g3[tid] * rsqrtf(v3[tid] + EPSF);
        sS[128 + tid] = s;
        sB3[tid] = (b3[tid] - m3[tid]) * s + bt3[tid];
    }
    __syncthreads();

    for (int i = tid; i < CIN_ * 64; i += 128) {
        int c = i >> 6, o = i & 63;
        sW1[i] = w1[o * CIN_ + c] * sS[o];
    }
    for (int i = tid; i < 64 * 64; i += 128) {
        int c = i >> 6, o = i & 63;
        sW2[i] = w2[o * 64 + c] * sS[64 + o];
    }
    for (int i = tid; i < 64 * 128; i += 128) {
        int c = i >> 7, o = i & 127;
        sW3[i] = w3[o * 64 + c] * sS[128 + o];
    }
    __syncthreads();

    const int warp = tid >> 5;
    const int lane = tid & 31;
    float* myX = sX + tid * XS;
    float* myY = sY + tid * YS;

    for (int it = 0; it < CPW; it++) {
        const int ci = blockIdx.x * (WPB * CPW) + warp * CPW + it;
        const int b  = ci >> 11;   // / 2048

        // ---- gather: stage this lane's k-slot input row into SMEM ----
        const int  ig    = g_gidx[(size_t)ci * K_ + lane];
        const bool valid = (ig >= 0);
        const int  ip    = valid ? ig : 0;
        const float* ctr = centers + (size_t)ci * 3;
        const float* p   = xyzs + ((size_t)b * N_ + ip) * 3;
        myX[0] = valid ? (p[0] - ctr[0]) : 0.0f;
        myX[1] = valid ? (p[1] - ctr[1]) : 0.0f;
        myX[2] = valid ? (p[2] - ctr[2]) : 0.0f;
        const float4* f4 = (const float4*)(feats + ((size_t)b * N_ + ip) * F_);
#pragma unroll
        for (int q = 0; q < 16; q++) {
            float4 t = f4[q];
            myX[3 + 4 * q + 0] = valid ? t.x : 0.0f;
            myX[3 + 4 * q + 1] = valid ? t.y : 0.0f;
            myX[3 + 4 * q + 2] = valid ? t.z : 0.0f;
            myX[3 + 4 * q + 3] = valid ? t.w : 0.0f;
        }

        ull acc[32];

        // ---- layer 1: 67 -> 64 ----
#pragma unroll
        for (int t = 0; t < 32; t++) acc[t] = ((const ull*)sB1)[t];
#pragma unroll 1
        for (int c = 0; c < CIN_; c++) step64(acc, myX[c], sW1 + c * 64);
#pragma unroll
        for (int t = 0; t < 32; t++) {
            float lo, hi; upk2(acc[t], lo, hi);
            myY[2 * t]     = fmaxf(lo, 0.0f);
            myY[2 * t + 1] = fmaxf(hi, 0.0f);
        }

        // ---- layer 2: 64 -> 64 ----
#pragma unroll
        for (int t = 0; t < 32; t++) acc[t] = ((const ull*)sB2)[t];
#pragma unroll 1
        for (int c = 0; c < 64; c++) step64(acc, myY[c], sW2 + c * 64);
#pragma unroll
        for (int t = 0; t < 32; t++) {
            float lo, hi; upk2(acc[t], lo, hi);
            myY[2 * t]     = fmaxf(lo, 0.0f);
            myY[2 * t + 1] = fmaxf(hi, 0.0f);
        }

        // ---- layer 3: 64 -> 128 in two halves, relu, warp max over K ----
        float* op = outf + (size_t)ci * 128;
#pragma unroll 1
        for (int h = 0; h < 2; h++) {
#pragma unroll
            for (int t = 0; t < 32; t++) acc[t] = ((const ull*)(sB3 + h * 64))[t];
#pragma unroll 1
            for (int c = 0; c < 64; c++) step64(acc, myY[c], sW3 + c * 128 + h * 64);
#pragma unroll
            for (int t = 0; t < 32; t++) {
                float lo, hi; upk2(acc[t], lo, hi);
                unsigned ulo = __float_as_uint(fmaxf(lo, 0.0f)) & 0x7fffffffu;
                unsigned uhi = __float_as_uint(fmaxf(hi, 0.0f)) & 0x7fffffffu;
                float rlo = __uint_as_float(__reduce_max_sync(0xffffffffu, ulo));
                float rhi = __uint_as_float(__reduce_max_sync(0xffffffffu, uhi));
                if (lane == 0)
                    *(float2*)(op + h * 64 + 2 * t) = make_float2(rlo, rhi);
            }
        }
    }
}

// ---------------------------------------------------------------------------
extern "C" void kernel_launch(void* const* d_in, const int* in_sizes, int n_in,
                              void* d_out, int out_size)
{
    const float* xyzs  = (const float*)d_in[0];
    const float* feats = (const float*)d_in[1];
    const float* w1 = (const float*)d_in[2];
    const float* b1 = (const float*)d_in[3];
    const float* g1 = (const float*)d_in[4];
    const float* bt1= (const float*)d_in[5];
    const float* m1 = (const float*)d_in[6];
    const float* v1 = (const float*)d_in[7];
    const float* w2 = (const float*)d_in[8];
    const float* b2 = (const float*)d_in[9];
    const float* g2 = (const float*)d_in[10];
    const float* bt2= (const float*)d_in[11];
    const float* m2 = (const float*)d_in[12];
    const float* v2 = (const float*)d_in[13];
    const float* w3 = (const float*)d_in[14];
    const float* b3 = (const float*)d_in[15];
    const float* g3 = (const float*)d_in[16];
    const float* bt3= (const float*)d_in[17];
    const float* m3 = (const float*)d_in[18];
    const float* v3 = (const float*)d_in[19];

    float* outc = (float*)d_out;                      // [B,S,3]
    float* outf = outc + (size_t)B_ * S_ * 3;         // [B,S,128]

    const int FPS_SMEM  = 3 * N_ * sizeof(float);                 // 96 KB
    const int BALL_SMEM = N_ * sizeof(float4);                    // 128 KB
    const int MLP_SMEM  = (CIN_ * 64 + 64 * 64 + 64 * 128 + 64 + 64 + 128 + 256
                           + 128 * XS + 128 * YS) * sizeof(float);

    cudaFuncSetAttribute(fps_kernel,  cudaFuncAttributeMaxDynamicSharedMemorySize, FPS_SMEM);
    cudaFuncSetAttribute(ball_kernel, cudaFuncAttributeMaxDynamicSharedMemorySize, BALL_SMEM);
    cudaFuncSetAttribute(mlp_kernel,  cudaFuncAttributeMaxDynamicSharedMemorySize, MLP_SMEM);

    fps_kernel <<<B_, 1024, FPS_SMEM>>>(xyzs, outc);
    ball_kernel<<<(B_ * S_) / 16, 512, BALL_SMEM>>>(xyzs, outc);
    mlp_kernel <<<(B_ * S_) / (WPB * CPW), 128, MLP_SMEM>>>(
        xyzs, feats,
        w1, b1, g1, bt1, m1, v1,
        w2, b2, g2, bt2, m2, v2,
        w3, b3, g3, bt3, m3, v3,
        outc, outf);
}

// round 8
// speedup vs baseline: 1.9590x; 1.0026x over previous
#include <cuda_runtime.h>
#include <cstdint>
#include <cstddef>

#define B_   8
#define N_   8192
#define S_   2048
#define K_   32
#define F_   64
#define CIN_ 67
#define EPSF 1e-5f

typedef unsigned long long ull;

// scratch: group indices (-1 padded), 2 MB static device array
__device__ int g_gidx[B_ * S_ * K_];

// ---- packed f32x2 helpers (per-lane IEEE rn, bit-identical to scalar) ----
__device__ __forceinline__ ull pk2(float lo, float hi) {
    ull r; asm("mov.b64 %0, {%1, %2};" : "=l"(r) : "f"(lo), "f"(hi)); return r;
}
__device__ __forceinline__ void upk2(ull v, float& lo, float& hi) {
    asm("mov.b64 {%0, %1}, %2;" : "=f"(lo), "=f"(hi) : "l"(v));
}
__device__ __forceinline__ ull add2(ull a, ull b) {
    ull r; asm("add.rn.f32x2 %0, %1, %2;" : "=l"(r) : "l"(a), "l"(b)); return r;
}
__device__ __forceinline__ ull mul2(ull a, ull b) {
    ull r; asm("mul.rn.f32x2 %0, %1, %2;" : "=l"(r) : "l"(a), "l"(b)); return r;
}
__device__ __forceinline__ ull fma2(ull a, ull b, ull c) {
    ull r; asm("fma.rn.f32x2 %0, %1, %2, %3;" : "=l"(r) : "l"(a), "l"(b), "l"(c)); return r;
}

// ---------------------------------------------------------------------------
// Kernel 1: farthest point sampling. One CTA per batch, 1024 threads,
// 8 points per thread (4 packed pairs). ONE barrier per step.
// Distance: per-lane rn ops in canonical order ((dx*dx+dy*dy)+dz*dz);
// min/max scalar (alu-pipe FMNMX, dual-issues against fma-pipe FFMA2).
// ---------------------------------------------------------------------------
__global__ __launch_bounds__(1024, 1)
void fps_kernel(const float* __restrict__ xyzs, float* __restrict__ outc)
{
    extern __shared__ float sm1[];
    float* sx = sm1;
    float* sy = sm1 + N_;
    float* sz = sm1 + 2 * N_;
    __shared__ ull swp[2][32];

    const int b    = blockIdx.x;
    const int tid  = threadIdx.x;
    const int lane = tid & 31;
    const int wid  = tid >> 5;
    const float* xyz = xyzs + (size_t)b * N_ * 3;

    ull px2[4], py2[4], pz2[4];
    float mind[8];
#pragma unroll
    for (int p = 0; p < 4; p++) {
        int i0 = tid + (2 * p) * 1024;
        int i1 = tid + (2 * p + 1) * 1024;
        float X0 = xyz[i0 * 3 + 0], Y0 = xyz[i0 * 3 + 1], Z0 = xyz[i0 * 3 + 2];
        float X1 = xyz[i1 * 3 + 0], Y1 = xyz[i1 * 3 + 1], Z1 = xyz[i1 * 3 + 2];
        px2[p] = pk2(X0, X1); py2[p] = pk2(Y0, Y1); pz2[p] = pk2(Z0, Z1);
        sx[i0] = X0; sy[i0] = Y0; sz[i0] = Z0;
        sx[i1] = X1; sy[i1] = Y1; sz[i1] = Z1;
        mind[2 * p] = 1e10f; mind[2 * p + 1] = 1e10f;
    }
    __syncthreads();

    float cx = sx[0], cy = sy[0], cz = sz[0];
    if (tid == 0) {
        float* o = outc + (size_t)b * S_ * 3;
        o[0] = cx; o[1] = cy; o[2] = cz;
    }

    for (int s = 1; s < S_; s++) {
        ull ncx2 = pk2(-cx, -cx), ncy2 = pk2(-cy, -cy), ncz2 = pk2(-cz, -cz);

        float bv = -1.0f;
#pragma unroll
        for (int p = 0; p < 4; p++) {
            ull dx2 = add2(px2[p], ncx2);
            ull dy2 = add2(py2[p], ncy2);
            ull dz2 = add2(pz2[p], ncz2);
            ull d2  = add2(add2(mul2(dx2, dx2), mul2(dy2, dy2)), mul2(dz2, dz2));
            float dlo, dhi; upk2(d2, dlo, dhi);
            float m0 = fminf(mind[2 * p],     dlo);
            float m1 = fminf(mind[2 * p + 1], dhi);
            mind[2 * p]     = m0;
            mind[2 * p + 1] = m1;
            bv = fmaxf(bv, fmaxf(m0, m1));
        }
        // distances >= 0 -> float order == unsigned bit order
        unsigned wmax  = __reduce_max_sync(0xffffffffu, __float_as_uint(bv));
        float    wmaxf = __uint_as_float(wmax);
        unsigned cand  = 0xffffffffu;
#pragma unroll
        for (int j = 7; j >= 0; j--)
            if (mind[j] == wmaxf) cand = (unsigned)(tid + j * 1024);
        cand = __reduce_min_sync(0xffffffffu, cand);
        if (lane == 0) swp[s & 1][wid] = ((ull)wmax << 32) | (ull)cand;
        __syncthreads();

        ull key = swp[s & 1][lane];
        unsigned hi = (unsigned)(key >> 32), lo = (unsigned)key;
        unsigned ghi  = __reduce_max_sync(0xffffffffu, hi);
        unsigned gidx = __reduce_min_sync(0xffffffffu, (hi == ghi) ? lo : 0xffffffffu);

        cx = sx[gidx]; cy = sy[gidx]; cz = sz[gidx];
        if (tid == 0) {
            float* o = outc + ((size_t)b * S_ + s) * 3;
            o[0] = cx; o[1] = cy; o[2] = cz;
        }
    }
}

// ---------------------------------------------------------------------------
// Kernel 2: ball query, warp-per-center ballot scan (unchanged from R6).
// ---------------------------------------------------------------------------
__global__ __launch_bounds__(512)
void ball_kernel(const float* __restrict__ xyzs, const float* __restrict__ centers)
{
    extern __shared__ float4 sp[];   // [N_] : 128 KB

    const int cbase = blockIdx.x * 16;
    const int b     = cbase >> 11;           // / 2048 (16 | 2048, no cross-batch)
    const float* xyz = xyzs + (size_t)b * N_ * 3;

    for (int i = threadIdx.x; i < N_; i += 512) {
        float X = xyz[i * 3 + 0];
        float Y = xyz[i * 3 + 1];
        float Z = xyz[i * 3 + 2];
        float nrm = __fadd_rn(__fadd_rn(__fmul_rn(X, X), __fmul_rn(Y, Y)),
                              __fmul_rn(Z, Z));
        sp[i] = make_float4(X, Y, Z, nrm);
    }
    __syncthreads();

    const int warp = threadIdx.x >> 5;
    const int lane = threadIdx.x & 31;
    const int ci   = cbase + warp;
    const float* c = centers + (size_t)ci * 3;
    const float cx = c[0], cy = c[1], cz = c[2];
    const float cc = __fadd_rn(__fadd_rn(__fmul_rn(cx, cx), __fmul_rn(cy, cy)),
                               __fmul_rn(cz, cz));
    const float R2 = 0.2f * 0.2f;
    const unsigned below = (1u << lane) - 1u;

    int cnt = 0;
    for (int chunk = 0; chunk < N_ / 32; chunk++) {
        int n = chunk * 32 + lane;
        float4 p = sp[n];
        float dot = __fadd_rn(__fadd_rn(__fmul_rn(cx, p.x), __fmul_rn(cy, p.y)),
                              __fmul_rn(cz, p.z));
        float d2  = __fsub_rn(__fadd_rn(cc, p.w), __fmul_rn(2.0f, dot));
        bool hit = (d2 <= R2);
        unsigned m = __ballot_sync(0xffffffffu, hit);
        int pos = cnt + __popc(m & below);
        if (hit && pos < K_) g_gidx[(size_t)ci * K_ + pos] = n;
        cnt += __popc(m);
        if (cnt >= K_) break;
    }
    for (int t = cnt + lane; t < K_; t += 32) g_gidx[(size_t)ci * K_ + t] = -1;
}

// ---------------------------------------------------------------------------
// Kernel 3: gather + 3-layer MLP (BN folded) + max over K.
// 4 warps/block, CPW centers per warp, lane = k slot. Single staging array
// (x rows reused for y after layer1 -> 104 KB smem -> 2 CTAs/SM).
// FMA order per output channel identical to previous rounds (bit-exact).
// ---------------------------------------------------------------------------
#define WPB 4
#define CPW 2
#define XS  69   // staging row stride (67 used), odd vs 32 banks -> conflict-free

__device__ __forceinline__ void step64(ull* __restrict__ acc, float xv,
                                       const float* __restrict__ wrow)
{
    ull xv2 = pk2(xv, xv);
    const ulonglong2* wp = (const ulonglong2*)wrow;
#pragma unroll
    for (int t = 0; t < 16; t++) {
        ulonglong2 w = wp[t];
        acc[2 * t]     = fma2(xv2, w.x, acc[2 * t]);
        acc[2 * t + 1] = fma2(xv2, w.y, acc[2 * t + 1]);
    }
}

__global__ __launch_bounds__(128, 2)
void mlp_kernel(const float* __restrict__ xyzs, const float* __restrict__ feats,
                const float* __restrict__ w1, const float* __restrict__ b1,
                const float* __restrict__ g1, const float* __restrict__ bt1,
                const float* __restrict__ m1, const float* __restrict__ v1,
                const float* __restrict__ w2, const float* __restrict__ b2,
                const float* __restrict__ g2, const float* __restrict__ bt2,
                const float* __restrict__ m2, const float* __restrict__ v2,
                const float* __restrict__ w3, const float* __restrict__ b3,
                const float* __restrict__ g3, const float* __restrict__ bt3,
                const float* __restrict__ m3, const float* __restrict__ v3,
                const float* __restrict__ centers, float* __restrict__ outf)
{
    extern __shared__ float sm3[];
    float* sW1 = sm3;                 // [67][64] transposed: sW1[c*64+o]
    float* sW2 = sW1 + CIN_ * 64;     // [64][64]
    float* sW3 = sW2 + 64 * 64;       // [64][128]
    float* sB1 = sW3 + 64 * 128;      // 64
    float* sB2 = sB1 + 64;            // 64
    float* sB3 = sB2 + 64;            // 128
    float* sS  = sB3 + 128;           // 256 scales
    float* sX  = sS + 256;            // [128 threads][XS] staged x (reused for y)

    const int tid = threadIdx.x;

    if (tid < 64) {
        float s = g1[tid] * rsqrtf(v1[tid] + EPSF);
        sS[tid] = s;
        sB1[tid] = (b1[tid] - m1[tid]) * s + bt1[tid];
    } else {
        int o = tid - 64;
        float s = g2[o] * rsqrtf(v2[o] + EPSF);
        sS[64 + o] = s;
        sB2[o] = (b2[o] - m2[o]) * s + bt2[o];
    }
    {
        float s = g3[tid] * rsqrtf(v3[tid] + EPSF);
        sS[128 + tid] = s;
        sB3[tid] = (b3[tid] - m3[tid]) * s + bt3[tid];
    }
    __syncthreads();

    for (int i = tid; i < CIN_ * 64; i += 128) {
        int c = i >> 6, o = i & 63;
        sW1[i] = w1[o * CIN_ + c] * sS[o];
    }
    for (int i = tid; i < 64 * 64; i += 128) {
        int c = i >> 6, o = i & 63;
        sW2[i] = w2[o * 64 + c] * sS[64 + o];
    }
    for (int i = tid; i < 64 * 128; i += 128) {
        int c = i >> 7, o = i & 127;
        sW3[i] = w3[o * 64 + c] * sS[128 + o];
    }
    __syncthreads();

    const int warp = tid >> 5;
    const int lane = tid & 31;
    float* myX = sX + tid * XS;   // this thread's staging row (x, then y)

    for (int it = 0; it < CPW; it++) {
        const int ci = blockIdx.x * (WPB * CPW) + warp * CPW + it;
        const int b  = ci >> 11;   // / 2048

        // ---- gather: stage this lane's k-slot input row into SMEM ----
        const int  ig    = g_gidx[(size_t)ci * K_ + lane];
        const bool valid = (ig >= 0);
        const int  ip    = valid ? ig : 0;
        const float* ctr = centers + (size_t)ci * 3;
        const float* p   = xyzs + ((size_t)b * N_ + ip) * 3;
        myX[0] = valid ? (p[0] - ctr[0]) : 0.0f;
        myX[1] = valid ? (p[1] - ctr[1]) : 0.0f;
        myX[2] = valid ? (p[2] - ctr[2]) : 0.0f;
        const float4* f4 = (const float4*)(feats + ((size_t)b * N_ + ip) * F_);
#pragma unroll
        for (int q = 0; q < 16; q++) {
            float4 t = f4[q];
            myX[3 + 4 * q + 0] = valid ? t.x : 0.0f;
            myX[3 + 4 * q + 1] = valid ? t.y : 0.0f;
            myX[3 + 4 * q + 2] = valid ? t.z : 0.0f;
            myX[3 + 4 * q + 3] = valid ? t.w : 0.0f;
        }

        ull acc[32];

        // ---- layer 1: 67 -> 64 (reads myX[0..66] fully, then overwrites) ----
#pragma unroll
        for (int t = 0; t < 32; t++) acc[t] = ((const ull*)sB1)[t];
#pragma unroll 1
        for (int c = 0; c < CIN_; c++) step64(acc, myX[c], sW1 + c * 64);
#pragma unroll
        for (int t = 0; t < 32; t++) {
            float lo, hi; upk2(acc[t], lo, hi);
            myX[2 * t]     = fmaxf(lo, 0.0f);
            myX[2 * t + 1] = fmaxf(hi, 0.0f);
        }

        // ---- layer 2: 64 -> 64 ----
#pragma unroll
        for (int t = 0; t < 32; t++) acc[t] = ((const ull*)sB2)[t];
#pragma unroll 1
        for (int c = 0; c < 64; c++) step64(acc, myX[c], sW2 + c * 64);
#pragma unroll
        for (int t = 0; t < 32; t++) {
            float lo, hi; upk2(acc[t], lo, hi);
            myX[2 * t]     = fmaxf(lo, 0.0f);
            myX[2 * t + 1] = fmaxf(hi, 0.0f);
        }

        // ---- layer 3: 64 -> 128 in two halves, relu, warp max over K ----
        float* op = outf + (size_t)ci * 128;
#pragma unroll 1
        for (int h = 0; h < 2; h++) {
#pragma unroll
            for (int t = 0; t < 32; t++) acc[t] = ((const ull*)(sB3 + h * 64))[t];
#pragma unroll 1
            for (int c = 0; c < 64; c++) step64(acc, myX[c], sW3 + c * 128 + h * 64);
#pragma unroll
            for (int t = 0; t < 32; t++) {
                float lo, hi; upk2(acc[t], lo, hi);
                unsigned ulo = __float_as_uint(fmaxf(lo, 0.0f)) & 0x7fffffffu;
                unsigned uhi = __float_as_uint(fmaxf(hi, 0.0f)) & 0x7fffffffu;
                float rlo = __uint_as_float(__reduce_max_sync(0xffffffffu, ulo));
                float rhi = __uint_as_float(__reduce_max_sync(0xffffffffu, uhi));
                if (lane == 0)
                    *(float2*)(op + h * 64 + 2 * t) = make_float2(rlo, rhi);
            }
        }
    }
}

// ---------------------------------------------------------------------------
extern "C" void kernel_launch(void* const* d_in, const int* in_sizes, int n_in,
                              void* d_out, int out_size)
{
    const float* xyzs  = (const float*)d_in[0];
    const float* feats = (const float*)d_in[1];
    const float* w1 = (const float*)d_in[2];
    const float* b1 = (const float*)d_in[3];
    const float* g1 = (const float*)d_in[4];
    const float* bt1= (const float*)d_in[5];
    const float* m1 = (const float*)d_in[6];
    const float* v1 = (const float*)d_in[7];
    const float* w2 = (const float*)d_in[8];
    const float* b2 = (const float*)d_in[9];
    const float* g2 = (const float*)d_in[10];
    const float* bt2= (const float*)d_in[11];
    const float* m2 = (const float*)d_in[12];
    const float* v2 = (const float*)d_in[13];
    const float* w3 = (const float*)d_in[14];
    const float* b3 = (const float*)d_in[15];
    const float* g3 = (const float*)d_in[16];
    const float* bt3= (const float*)d_in[17];
    const float* m3 = (const float*)d_in[18];
    const float* v3 = (const float*)d_in[19];

    float* outc = (float*)d_out;                      // [B,S,3]
    float* outf = outc + (size_t)B_ * S_ * 3;         // [B,S,128]

    const int FPS_SMEM  = 3 * N_ * sizeof(float);                 // 96 KB
    const int BALL_SMEM = N_ * sizeof(float4);                    // 128 KB
    const int MLP_SMEM  = (CIN_ * 64 + 64 * 64 + 64 * 128 + 64 + 64 + 128 + 256
                           + 128 * XS) * sizeof(float);           // ~104 KB

    cudaFuncSetAttribute(fps_kernel,  cudaFuncAttributeMaxDynamicSharedMemorySize, FPS_SMEM);
    cudaFuncSetAttribute(ball_kernel, cudaFuncAttributeMaxDynamicSharedMemorySize, BALL_SMEM);
    cudaFuncSetAttribute(mlp_kernel,  cudaFuncAttributeMaxDynamicSharedMemorySize, MLP_SMEM);

    fps_kernel <<<B_, 1024, FPS_SMEM>>>(xyzs, outc);
    ball_kernel<<<(B_ * S_) / 16, 512, BALL_SMEM>>>(xyzs, outc);
    mlp_kernel <<<(B_ * S_) / (WPB * CPW), 128, MLP_SMEM>>>(
        xyzs, feats,
        w1, b1, g1, bt1, m1, v1,
        w2, b2, g2, bt2, m2, v2,
        w3, b3, g3, bt3, m3, v3,
        outc, outf);
}

// round 9
// speedup vs baseline: 2.8370x; 1.4482x over previous
#include <cuda_runtime.h>
#include <cstdint>
#include <cstddef>

#define B_   8
#define N_   8192
#define S_   2048
#define K_   32
#define F_   64
#define CIN_ 67
#define EPSF 1e-5f

#define CH   8           // pipeline chunks
#define CS   (S_ / CH)   // 256 centers per batch per chunk

typedef unsigned long long ull;

// scratch
__device__ int   g_gidx[B_ * S_ * K_];
__device__ float g_mind[B_][N_];

// ---- packed f32x2 helpers (per-lane IEEE rn, bit-identical to scalar) ----
__device__ __forceinline__ ull pk2(float lo, float hi) {
    ull r; asm("mov.b64 %0, {%1, %2};" : "=l"(r) : "f"(lo), "f"(hi)); return r;
}
__device__ __forceinline__ void upk2(ull v, float& lo, float& hi) {
    asm("mov.b64 {%0, %1}, %2;" : "=f"(lo), "=f"(hi) : "l"(v));
}
__device__ __forceinline__ ull add2(ull a, ull b) {
    ull r; asm("add.rn.f32x2 %0, %1, %2;" : "=l"(r) : "l"(a), "l"(b)); return r;
}
__device__ __forceinline__ ull mul2(ull a, ull b) {
    ull r; asm("mul.rn.f32x2 %0, %1, %2;" : "=l"(r) : "l"(a), "l"(b)); return r;
}
__device__ __forceinline__ ull fma2(ull a, ull b, ull c) {
    ull r; asm("fma.rn.f32x2 %0, %1, %2, %3;" : "=l"(r) : "l"(a), "l"(b), "l"(c)); return r;
}

// ---------------------------------------------------------------------------
// Kernel 1: FPS chunk [s0, s1). One CTA per batch, 1024 threads, 8 pts/thread.
// mind persisted in g_mind between chunks (bit-exact). Distance: per-lane rn
// ops in canonical order ((dx*dx+dy*dy)+dz*dz). One barrier per step.
// ---------------------------------------------------------------------------
__global__ __launch_bounds__(1024, 1)
void fps_kernel(const float* __restrict__ xyzs, float* __restrict__ outc,
                int s0, int s1, int first)
{
    extern __shared__ float sm1[];
    float* sx = sm1;
    float* sy = sm1 + N_;
    float* sz = sm1 + 2 * N_;
    __shared__ ull swp[2][32];

    const int b    = blockIdx.x;
    const int tid  = threadIdx.x;
    const int lane = tid & 31;
    const int wid  = tid >> 5;
    const float* xyz = xyzs + (size_t)b * N_ * 3;

    ull px2[4], py2[4], pz2[4];
    float mind[8];
#pragma unroll
    for (int p = 0; p < 4; p++) {
        int i0 = tid + (2 * p) * 1024;
        int i1 = tid + (2 * p + 1) * 1024;
        float X0 = xyz[i0 * 3 + 0], Y0 = xyz[i0 * 3 + 1], Z0 = xyz[i0 * 3 + 2];
        float X1 = xyz[i1 * 3 + 0], Y1 = xyz[i1 * 3 + 1], Z1 = xyz[i1 * 3 + 2];
        px2[p] = pk2(X0, X1); py2[p] = pk2(Y0, Y1); pz2[p] = pk2(Z0, Z1);
        sx[i0] = X0; sy[i0] = Y0; sz[i0] = Z0;
        sx[i1] = X1; sy[i1] = Y1; sz[i1] = Z1;
        if (first) {
            mind[2 * p] = 1e10f; mind[2 * p + 1] = 1e10f;
        } else {
            mind[2 * p]     = g_mind[b][i0];
            mind[2 * p + 1] = g_mind[b][i1];
        }
    }
    __syncthreads();

    float cx, cy, cz;
    if (first) {
        cx = sx[0]; cy = sy[0]; cz = sz[0];
        if (tid == 0) {
            float* o = outc + (size_t)b * S_ * 3;
            o[0] = cx; o[1] = cy; o[2] = cz;
        }
    } else {
        const float* o = outc + ((size_t)b * S_ + (s0 - 1)) * 3;
        cx = o[0]; cy = o[1]; cz = o[2];
    }

    for (int s = s0; s < s1; s++) {
        ull ncx2 = pk2(-cx, -cx), ncy2 = pk2(-cy, -cy), ncz2 = pk2(-cz, -cz);

        float bv = -1.0f;
#pragma unroll
        for (int p = 0; p < 4; p++) {
            ull dx2 = add2(px2[p], ncx2);
            ull dy2 = add2(py2[p], ncy2);
            ull dz2 = add2(pz2[p], ncz2);
            ull d2  = add2(add2(mul2(dx2, dx2), mul2(dy2, dy2)), mul2(dz2, dz2));
            float dlo, dhi; upk2(d2, dlo, dhi);
            float m0 = fminf(mind[2 * p],     dlo);
            float m1 = fminf(mind[2 * p + 1], dhi);
            mind[2 * p]     = m0;
            mind[2 * p + 1] = m1;
            bv = fmaxf(bv, fmaxf(m0, m1));
        }
        // distances >= 0 -> float order == unsigned bit order
        unsigned wmax  = __reduce_max_sync(0xffffffffu, __float_as_uint(bv));
        float    wmaxf = __uint_as_float(wmax);
        unsigned cand  = 0xffffffffu;
        if (__float_as_uint(bv) == wmax) {   // only holders scan
#pragma unroll
            for (int j = 7; j >= 0; j--)
                if (mind[j] == wmaxf) cand = (unsigned)(tid + j * 1024);
        }
        cand = __reduce_min_sync(0xffffffffu, cand);
        if (lane == 0) swp[s & 1][wid] = ((ull)wmax << 32) | (ull)cand;
        __syncthreads();

        ull key = swp[s & 1][lane];
        unsigned hi = (unsigned)(key >> 32), lo = (unsigned)key;
        unsigned ghi  = __reduce_max_sync(0xffffffffu, hi);
        unsigned gidx = __reduce_min_sync(0xffffffffu, (hi == ghi) ? lo : 0xffffffffu);

        cx = sx[gidx]; cy = sy[gidx]; cz = sz[gidx];
        if (tid == 0) {
            float* o = outc + ((size_t)b * S_ + s) * 3;
            o[0] = cx; o[1] = cy; o[2] = cz;
        }
    }

    // persist mind for the next chunk
#pragma unroll
    for (int p = 0; p < 4; p++) {
        g_mind[b][tid + (2 * p) * 1024]     = mind[2 * p];
        g_mind[b][tid + (2 * p + 1) * 1024] = mind[2 * p + 1];
    }
}

// ---------------------------------------------------------------------------
// Kernel 2: ball query chunk, warp-per-center ballot scan.
// grid = B_ * (CS/16) blocks of 512 threads (16 warps = 16 centers/block).
// ---------------------------------------------------------------------------
__global__ __launch_bounds__(512)
void ball_kernel(const float* __restrict__ xyzs, const float* __restrict__ centers,
                 int s0)
{
    extern __shared__ float4 sp[];   // [N_] : 128 KB

    const int bpb  = CS / 16;               // blocks per batch
    const int b    = blockIdx.x / bpb;
    const int soff = (blockIdx.x % bpb) * 16;
    const float* xyz = xyzs + (size_t)b * N_ * 3;

    for (int i = threadIdx.x; i < N_; i += 512) {
        float X = xyz[i * 3 + 0];
        float Y = xyz[i * 3 + 1];
        float Z = xyz[i * 3 + 2];
        float nrm = __fadd_rn(__fadd_rn(__fmul_rn(X, X), __fmul_rn(Y, Y)),
                              __fmul_rn(Z, Z));
        sp[i] = make_float4(X, Y, Z, nrm);
    }
    __syncthreads();

    const int warp = threadIdx.x >> 5;
    const int lane = threadIdx.x & 31;
    const int ci   = b * S_ + s0 + soff + warp;
    const float* c = centers + (size_t)ci * 3;
    const float cx = c[0], cy = c[1], cz = c[2];
    const float cc = __fadd_rn(__fadd_rn(__fmul_rn(cx, cx), __fmul_rn(cy, cy)),
                               __fmul_rn(cz, cz));
    const float R2 = 0.2f * 0.2f;
    const unsigned below = (1u << lane) - 1u;

    int cnt = 0;
    for (int chunk = 0; chunk < N_ / 32; chunk++) {
        int n = chunk * 32 + lane;
        float4 p = sp[n];
        float dot = __fadd_rn(__fadd_rn(__fmul_rn(cx, p.x), __fmul_rn(cy, p.y)),
                              __fmul_rn(cz, p.z));
        float d2  = __fsub_rn(__fadd_rn(cc, p.w), __fmul_rn(2.0f, dot));
        bool hit = (d2 <= R2);
        unsigned m = __ballot_sync(0xffffffffu, hit);
        int pos = cnt + __popc(m & below);
        if (hit && pos < K_) g_gidx[(size_t)ci * K_ + pos] = n;
        cnt += __popc(m);
        if (cnt >= K_) break;
    }
    for (int t = cnt + lane; t < K_; t += 32) g_gidx[(size_t)ci * K_ + t] = -1;
}

// ---------------------------------------------------------------------------
// Kernel 3: gather + 3-layer MLP (BN folded) + max over K, chunked.
// 4 warps/block, CPW centers per warp, lane = k slot. Single staging array.
// FMA order per output channel identical to previous rounds (bit-exact).
// ---------------------------------------------------------------------------
#define WPB 4
#define CPW 2
#define XS  69   // staging row stride (67 used), odd -> conflict-free

__device__ __forceinline__ void step64(ull* __restrict__ acc, float xv,
                                       const float* __restrict__ wrow)
{
    ull xv2 = pk2(xv, xv);
    const ulonglong2* wp = (const ulonglong2*)wrow;
#pragma unroll
    for (int t = 0; t < 16; t++) {
        ulonglong2 w = wp[t];
        acc[2 * t]     = fma2(xv2, w.x, acc[2 * t]);
        acc[2 * t + 1] = fma2(xv2, w.y, acc[2 * t + 1]);
    }
}

__global__ __launch_bounds__(128, 2)
void mlp_kernel(const float* __restrict__ xyzs, const float* __restrict__ feats,
                const float* __restrict__ w1, const float* __restrict__ b1,
                const float* __restrict__ g1, const float* __restrict__ bt1,
                const float* __restrict__ m1, const float* __restrict__ v1,
                const float* __restrict__ w2, const float* __restrict__ b2,
                const float* __restrict__ g2, const float* __restrict__ bt2,
                const float* __restrict__ m2, const float* __restrict__ v2,
                const float* __restrict__ w3, const float* __restrict__ b3,
                const float* __restrict__ g3, const float* __restrict__ bt3,
                const float* __restrict__ m3, const float* __restrict__ v3,
                const float* __restrict__ centers, float* __restrict__ outf,
                int s0)
{
    extern __shared__ float sm3[];
    float* sW1 = sm3;                 // [67][64] transposed: sW1[c*64+o]
    float* sW2 = sW1 + CIN_ * 64;     // [64][64]
    float* sW3 = sW2 + 64 * 64;       // [64][128]
    float* sB1 = sW3 + 64 * 128;      // 64
    float* sB2 = sB1 + 64;            // 64
    float* sB3 = sB2 + 64;            // 128
    float* sS  = sB3 + 128;           // 256 scales
    float* sX  = sS + 256;            // [128 threads][XS] staged x (reused for y)

    const int tid = threadIdx.x;

    if (tid < 64) {
        float s = g1[tid] * rsqrtf(v1[tid] + EPSF);
        sS[tid] = s;
        sB1[tid] = (b1[tid] - m1[tid]) * s + bt1[tid];
    } else {
        int o = tid - 64;
        float s = g2[o] * rsqrtf(v2[o] + EPSF);
        sS[64 + o] = s;
        sB2[o] = (b2[o] - m2[o]) * s + bt2[o];
    }
    {
        float s = g3[tid] * rsqrtf(v3[tid] + EPSF);
        sS[128 + tid] = s;
        sB3[tid] = (b3[tid] - m3[tid]) * s + bt3[tid];
    }
    __syncthreads();

    for (int i = tid; i < CIN_ * 64; i += 128) {
        int c = i >> 6, o = i & 63;
        sW1[i] = w1[o * CIN_ + c] * sS[o];
    }
    for (int i = tid; i < 64 * 64; i += 128) {
        int c = i >> 6, o = i & 63;
        sW2[i] = w2[o * 64 + c] * sS[64 + o];
    }
    for (int i = tid; i < 64 * 128; i += 128) {
        int c = i >> 7, o = i & 127;
        sW3[i] = w3[o * 64 + c] * sS[128 + o];
    }
    __syncthreads();

    const int warp = tid >> 5;
    const int lane = tid & 31;
    float* myX = sX + tid * XS;   // this thread's staging row (x, then y)

    const int pbb = CS / (WPB * CPW);             // blocks per batch
    const int b   = blockIdx.x / pbb;
    const int cb  = b * S_ + s0 + (blockIdx.x % pbb) * (WPB * CPW);

    for (int it = 0; it < CPW; it++) {
        const int ci = cb + warp * CPW + it;

        // ---- gather: stage this lane's k-slot input row into SMEM ----
        const int  ig    = g_gidx[(size_t)ci * K_ + lane];
        const bool valid = (ig >= 0);
        const int  ip    = valid ? ig : 0;
        const float* ctr = centers + (size_t)ci * 3;
        const float* p   = xyzs + ((size_t)b * N_ + ip) * 3;
        myX[0] = valid ? (p[0] - ctr[0]) : 0.0f;
        myX[1] = valid ? (p[1] - ctr[1]) : 0.0f;
        myX[2] = valid ? (p[2] - ctr[2]) : 0.0f;
        const float4* f4 = (const float4*)(feats + ((size_t)b * N_ + ip) * F_);
#pragma unroll
        for (int q = 0; q < 16; q++) {
            float4 t = f4[q];
            myX[3 + 4 * q + 0] = valid ? t.x : 0.0f;
            myX[3 + 4 * q + 1] = valid ? t.y : 0.0f;
            myX[3 + 4 * q + 2] = valid ? t.z : 0.0f;
            myX[3 + 4 * q + 3] = valid ? t.w : 0.0f;
        }

        ull acc[32];

        // ---- layer 1: 67 -> 64 ----
#pragma unroll
        for (int t = 0; t < 32; t++) acc[t] = ((const ull*)sB1)[t];
#pragma unroll 1
        for (int c = 0; c < CIN_; c++) step64(acc, myX[c], sW1 + c * 64);
#pragma unroll
        for (int t = 0; t < 32; t++) {
            float lo, hi; upk2(acc[t], lo, hi);
            myX[2 * t]     = fmaxf(lo, 0.0f);
            myX[2 * t + 1] = fmaxf(hi, 0.0f);
        }

        // ---- layer 2: 64 -> 64 ----
#pragma unroll
        for (int t = 0; t < 32; t++) acc[t] = ((const ull*)sB2)[t];
#pragma unroll 1
        for (int c = 0; c < 64; c++) step64(acc, myX[c], sW2 + c * 64);
#pragma unroll
        for (int t = 0; t < 32; t++) {
            float lo, hi; upk2(acc[t], lo, hi);
            myX[2 * t]     = fmaxf(lo, 0.0f);
            myX[2 * t + 1] = fmaxf(hi, 0.0f);
        }

        // ---- layer 3: 64 -> 128 in two halves, relu, warp max over K ----
        float* op = outf + (size_t)ci * 128;
#pragma unroll 1
        for (int h = 0; h < 2; h++) {
#pragma unroll
            for (int t = 0; t < 32; t++) acc[t] = ((const ull*)(sB3 + h * 64))[t];
#pragma unroll 1
            for (int c = 0; c < 64; c++) step64(acc, myX[c], sW3 + c * 128 + h * 64);
#pragma unroll
            for (int t = 0; t < 32; t++) {
                float lo, hi; upk2(acc[t], lo, hi);
                unsigned ulo = __float_as_uint(fmaxf(lo, 0.0f)) & 0x7fffffffu;
                unsigned uhi = __float_as_uint(fmaxf(hi, 0.0f)) & 0x7fffffffu;
                float rlo = __uint_as_float(__reduce_max_sync(0xffffffffu, ulo));
                float rhi = __uint_as_float(__reduce_max_sync(0xffffffffu, uhi));
                if (lane == 0)
                    *(float2*)(op + h * 64 + 2 * t) = make_float2(rlo, rhi);
            }
        }
    }
}

// ---------------------------------------------------------------------------
extern "C" void kernel_launch(void* const* d_in, const int* in_sizes, int n_in,
                              void* d_out, int out_size)
{
    const float* xyzs  = (const float*)d_in[0];
    const float* feats = (const float*)d_in[1];
    const float* w1 = (const float*)d_in[2];
    const float* b1 = (const float*)d_in[3];
    const float* g1 = (const float*)d_in[4];
    const float* bt1= (const float*)d_in[5];
    const float* m1 = (const float*)d_in[6];
    const float* v1 = (const float*)d_in[7];
    const float* w2 = (const float*)d_in[8];
    const float* b2 = (const float*)d_in[9];
    const float* g2 = (const float*)d_in[10];
    const float* bt2= (const float*)d_in[11];
    const float* m2 = (const float*)d_in[12];
    const float* v2 = (const float*)d_in[13];
    const float* w3 = (const float*)d_in[14];
    const float* b3 = (const float*)d_in[15];
    const float* g3 = (const float*)d_in[16];
    const float* bt3= (const float*)d_in[17];
    const float* m3 = (const float*)d_in[18];
    const float* v3 = (const float*)d_in[19];

    float* outc = (float*)d_out;                      // [B,S,3]
    float* outf = outc + (size_t)B_ * S_ * 3;         // [B,S,128]

    // FPS uses 96 KB but requests 192 KB to keep worker CTAs off its 8 SMs.
    const int FPS_SMEM  = 192 * 1024;
    const int BALL_SMEM = N_ * sizeof(float4);                    // 128 KB
    const int MLP_SMEM  = (CIN_ * 64 + 64 * 64 + 64 * 128 + 64 + 64 + 128 + 256
                           + 128 * XS) * sizeof(float);           // ~104 KB

    static cudaStream_t ws = nullptr;
    static cudaEvent_t  evF[CH];
    static cudaEvent_t  evJ;
    if (!ws) {
        cudaStreamCreateWithFlags(&ws, cudaStreamNonBlocking);
        for (int k = 0; k < CH; k++)
            cudaEventCreateWithFlags(&evF[k], cudaEventDisableTiming);
        cudaEventCreateWithFlags(&evJ, cudaEventDisableTiming);
        cudaFuncSetAttribute(fps_kernel,  cudaFuncAttributeMaxDynamicSharedMemorySize, FPS_SMEM);
        cudaFuncSetAttribute(ball_kernel, cudaFuncAttributeMaxDynamicSharedMemorySize, BALL_SMEM);
        cudaFuncSetAttribute(mlp_kernel,  cudaFuncAttributeMaxDynamicSharedMemorySize, MLP_SMEM);
    }

    for (int k = 0; k < CH; k++) {
        fps_kernel<<<B_, 1024, FPS_SMEM>>>(xyzs, outc,
                                           (k == 0) ? 1 : k * CS, (k + 1) * CS,
                                           (k == 0) ? 1 : 0);
        cudaEventRecord(evF[k], 0);
        cudaStreamWaitEvent(ws, evF[k], 0);
        ball_kernel<<<B_ * (CS / 16), 512, BALL_SMEM, ws>>>(xyzs, outc, k * CS);
        mlp_kernel <<<B_ * (CS / (WPB * CPW)), 128, MLP_SMEM, ws>>>(
            xyzs, feats,
            w1, b1, g1, bt1, m1, v1,
            w2, b2, g2, bt2, m2, v2,
            w3, b3, g3, bt3, m3, v3,
            outc, outf, k * CS);
    }
    cudaEventRecord(evJ, ws);
    cudaStreamWaitEvent(0, evJ, 0);
}

// round 10
// speedup vs baseline: 3.0161x; 1.0631x over previous
#include <cuda_runtime.h>
#include <cstdint>
#include <cstddef>

#define B_   8
#define N_   8192
#define S_   2048
#define K_   32
#define F_   64
#define CIN_ 67
#define EPSF 1e-5f

#define CH   8           // pipeline chunks
#define CS   (S_ / CH)   // 256 centers per batch per chunk

#define FTH  512         // FPS threads per CTA
#define NP   8           // packed pairs per thread (16 points)

typedef unsigned long long ull;

// scratch
__device__ int   g_gidx[B_ * S_ * K_];
__device__ float g_mind[B_][N_];

// ---- packed f32x2 helpers (per-lane IEEE rn, bit-identical to scalar) ----
__device__ __forceinline__ ull pk2(float lo, float hi) {
    ull r; asm("mov.b64 %0, {%1, %2};" : "=l"(r) : "f"(lo), "f"(hi)); return r;
}
__device__ __forceinline__ void upk2(ull v, float& lo, float& hi) {
    asm("mov.b64 {%0, %1}, %2;" : "=f"(lo), "=f"(hi) : "l"(v));
}
__device__ __forceinline__ ull add2(ull a, ull b) {
    ull r; asm("add.rn.f32x2 %0, %1, %2;" : "=l"(r) : "l"(a), "l"(b)); return r;
}
__device__ __forceinline__ ull mul2(ull a, ull b) {
    ull r; asm("mul.rn.f32x2 %0, %1, %2;" : "=l"(r) : "l"(a), "l"(b)); return r;
}
__device__ __forceinline__ ull fma2(ull a, ull b, ull c) {
    ull r; asm("fma.rn.f32x2 %0, %1, %2, %3;" : "=l"(r) : "l"(a), "l"(b), "l"(c)); return r;
}

// ---------------------------------------------------------------------------
// Kernel 1: FPS chunk [s0, s1). One CTA per batch, 512 threads, 16 pts/thread
// (8 packed pairs). mind persisted in g_mind between chunks (bit-exact).
// Distance: per-lane rn ops in canonical order ((dx*dx+dy*dy)+dz*dz).
// One barrier per step; two-level redux reduction, exact argmax tie-break.
// ---------------------------------------------------------------------------
__global__ __launch_bounds__(FTH, 1)
void fps_kernel(const float* __restrict__ xyzs, float* __restrict__ outc,
                int s0, int s1, int first)
{
    extern __shared__ float sm1[];
    float* sx = sm1;
    float* sy = sm1 + N_;
    float* sz = sm1 + 2 * N_;
    __shared__ ull swp[2][32];

    const int b    = blockIdx.x;
    const int tid  = threadIdx.x;
    const int lane = tid & 31;
    const int wid  = tid >> 5;          // 0..15
    const float* xyz = xyzs + (size_t)b * N_ * 3;

    // neutral keys for unused warp slots 16..31 (dist bits 0, idx ~0)
    if (tid < 32 && tid >= 16) {
        swp[0][tid] = 0xffffffffull;
        swp[1][tid] = 0xffffffffull;
    }

    ull px2[NP], py2[NP], pz2[NP];
    float mind[2 * NP];
#pragma unroll
    for (int p = 0; p < NP; p++) {
        int i0 = tid + (2 * p) * FTH;
        int i1 = tid + (2 * p + 1) * FTH;
        float X0 = xyz[i0 * 3 + 0], Y0 = xyz[i0 * 3 + 1], Z0 = xyz[i0 * 3 + 2];
        float X1 = xyz[i1 * 3 + 0], Y1 = xyz[i1 * 3 + 1], Z1 = xyz[i1 * 3 + 2];
        px2[p] = pk2(X0, X1); py2[p] = pk2(Y0, Y1); pz2[p] = pk2(Z0, Z1);
        sx[i0] = X0; sy[i0] = Y0; sz[i0] = Z0;
        sx[i1] = X1; sy[i1] = Y1; sz[i1] = Z1;
        if (first) {
            mind[2 * p] = 1e10f; mind[2 * p + 1] = 1e10f;
        } else {
            mind[2 * p]     = g_mind[b][i0];
            mind[2 * p + 1] = g_mind[b][i1];
        }
    }
    __syncthreads();

    float cx, cy, cz;
    if (first) {
        cx = sx[0]; cy = sy[0]; cz = sz[0];
        if (tid == 0) {
            float* o = outc + (size_t)b * S_ * 3;
            o[0] = cx; o[1] = cy; o[2] = cz;
        }
    } else {
        const float* o = outc + ((size_t)b * S_ + (s0 - 1)) * 3;
        cx = o[0]; cy = o[1]; cz = o[2];
    }

    for (int s = s0; s < s1; s++) {
        ull ncx2 = pk2(-cx, -cx), ncy2 = pk2(-cy, -cy), ncz2 = pk2(-cz, -cz);

        float bv = -1.0f;
#pragma unroll
        for (int p = 0; p < NP; p++) {
            ull dx2 = add2(px2[p], ncx2);
            ull dy2 = add2(py2[p], ncy2);
            ull dz2 = add2(pz2[p], ncz2);
            ull d2  = add2(add2(mul2(dx2, dx2), mul2(dy2, dy2)), mul2(dz2, dz2));
            float dlo, dhi; upk2(d2, dlo, dhi);
            float m0 = fminf(mind[2 * p],     dlo);
            float m1 = fminf(mind[2 * p + 1], dhi);
            mind[2 * p]     = m0;
            mind[2 * p + 1] = m1;
            bv = fmaxf(bv, fmaxf(m0, m1));
        }
        // distances >= 0 -> float order == unsigned bit order
        unsigned wmax  = __reduce_max_sync(0xffffffffu, __float_as_uint(bv));
        float    wmaxf = __uint_as_float(wmax);
        unsigned cand  = 0xffffffffu;
        if (__float_as_uint(bv) == wmax) {   // only holders scan
#pragma unroll
            for (int j = 2 * NP - 1; j >= 0; j--)
                if (mind[j] == wmaxf) cand = (unsigned)(tid + j * FTH);
        }
        cand = __reduce_min_sync(0xffffffffu, cand);
        if (lane == 0) swp[s & 1][wid] = ((ull)wmax << 32) | (ull)cand;
        __syncthreads();

        ull key = swp[s & 1][lane];
        unsigned hi = (unsigned)(key >> 32), lo = (unsigned)key;
        unsigned ghi  = __reduce_max_sync(0xffffffffu, hi);
        unsigned gidx = __reduce_min_sync(0xffffffffu, (hi == ghi) ? lo : 0xffffffffu);

        cx = sx[gidx]; cy = sy[gidx]; cz = sz[gidx];
        if (tid == 0) {
            float* o = outc + ((size_t)b * S_ + s) * 3;
            o[0] = cx; o[1] = cy; o[2] = cz;
        }
    }

    // persist mind for the next chunk
#pragma unroll
    for (int p = 0; p < NP; p++) {
        g_mind[b][tid + (2 * p) * FTH]     = mind[2 * p];
        g_mind[b][tid + (2 * p + 1) * FTH] = mind[2 * p + 1];
    }
}

// ---------------------------------------------------------------------------
// Kernel 2: ball query chunk, warp-per-center ballot scan.
// ---------------------------------------------------------------------------
__global__ __launch_bounds__(512)
void ball_kernel(const float* __restrict__ xyzs, const float* __restrict__ centers,
                 int s0)
{
    extern __shared__ float4 sp[];   // [N_] : 128 KB

    const int bpb  = CS / 16;               // blocks per batch
    const int b    = blockIdx.x / bpb;
    const int soff = (blockIdx.x % bpb) * 16;
    const float* xyz = xyzs + (size_t)b * N_ * 3;

    for (int i = threadIdx.x; i < N_; i += 512) {
        float X = xyz[i * 3 + 0];
        float Y = xyz[i * 3 + 1];
        float Z = xyz[i * 3 + 2];
        float nrm = __fadd_rn(__fadd_rn(__fmul_rn(X, X), __fmul_rn(Y, Y)),
                              __fmul_rn(Z, Z));
        sp[i] = make_float4(X, Y, Z, nrm);
    }
    __syncthreads();

    const int warp = threadIdx.x >> 5;
    const int lane = threadIdx.x & 31;
    const int ci   = b * S_ + s0 + soff + warp;
    const float* c = centers + (size_t)ci * 3;
    const float cx = c[0], cy = c[1], cz = c[2];
    const float cc = __fadd_rn(__fadd_rn(__fmul_rn(cx, cx), __fmul_rn(cy, cy)),
                               __fmul_rn(cz, cz));
    const float R2 = 0.2f * 0.2f;
    const unsigned below = (1u << lane) - 1u;

    int cnt = 0;
    for (int chunk = 0; chunk < N_ / 32; chunk++) {
        int n = chunk * 32 + lane;
        float4 p = sp[n];
        float dot = __fadd_rn(__fadd_rn(__fmul_rn(cx, p.x), __fmul_rn(cy, p.y)),
                              __fmul_rn(cz, p.z));
        float d2  = __fsub_rn(__fadd_rn(cc, p.w), __fmul_rn(2.0f, dot));
        bool hit = (d2 <= R2);
        unsigned m = __ballot_sync(0xffffffffu, hit);
        int pos = cnt + __popc(m & below);
        if (hit && pos < K_) g_gidx[(size_t)ci * K_ + pos] = n;
        cnt += __popc(m);
        if (cnt >= K_) break;
    }
    for (int t = cnt + lane; t < K_; t += 32) g_gidx[(size_t)ci * K_ + t] = -1;
}

// ---------------------------------------------------------------------------
// Kernel 3: gather + 3-layer MLP (BN folded) + max over K, chunked.
// ---------------------------------------------------------------------------
#define WPB 4
#define CPW 2
#define XS  69   // staging row stride (67 used), odd -> conflict-free

__device__ __forceinline__ void step64(ull* __restrict__ acc, float xv,
                                       const float* __restrict__ wrow)
{
    ull xv2 = pk2(xv, xv);
    const ulonglong2* wp = (const ulonglong2*)wrow;
#pragma unroll
    for (int t = 0; t < 16; t++) {
        ulonglong2 w = wp[t];
        acc[2 * t]     = fma2(xv2, w.x, acc[2 * t]);
        acc[2 * t + 1] = fma2(xv2, w.y, acc[2 * t + 1]);
    }
}

__global__ __launch_bounds__(128, 2)
void mlp_kernel(const float* __restrict__ xyzs, const float* __restrict__ feats,
                const float* __restrict__ w1, const float* __restrict__ b1,
                const float* __restrict__ g1, const float* __restrict__ bt1,
                const float* __restrict__ m1, const float* __restrict__ v1,
                const float* __restrict__ w2, const float* __restrict__ b2,
                const float* __restrict__ g2, const float* __restrict__ bt2,
                const float* __restrict__ m2, const float* __restrict__ v2,
                const float* __restrict__ w3, const float* __restrict__ b3,
                const float* __restrict__ g3, const float* __restrict__ bt3,
                const float* __restrict__ m3, const float* __restrict__ v3,
                const float* __restrict__ centers, float* __restrict__ outf,
                int s0)
{
    extern __shared__ float sm3[];
    float* sW1 = sm3;                 // [67][64] transposed: sW1[c*64+o]
    float* sW2 = sW1 + CIN_ * 64;     // [64][64]
    float* sW3 = sW2 + 64 * 64;       // [64][128]
    float* sB1 = sW3 + 64 * 128;      // 64
    float* sB2 = sB1 + 64;            // 64
    float* sB3 = sB2 + 64;            // 128
    float* sS  = sB3 + 128;           // 256 scales
    float* sX  = sS + 256;            // [128 threads][XS] staged x (reused for y)

    const int tid = threadIdx.x;

    if (tid < 64) {
        float s = g1[tid] * rsqrtf(v1[tid] + EPSF);
        sS[tid] = s;
        sB1[tid] = (b1[tid] - m1[tid]) * s + bt1[tid];
    } else {
        int o = tid - 64;
        float s = g2[o] * rsqrtf(v2[o] + EPSF);
        sS[64 + o] = s;
        sB2[o] = (b2[o] - m2[o]) * s + bt2[o];
    }
    {
        float s = g3[tid] * rsqrtf(v3[tid] + EPSF);
        sS[128 + tid] = s;
        sB3[tid] = (b3[tid] - m3[tid]) * s + bt3[tid];
    }
    __syncthreads();

    for (int i = tid; i < CIN_ * 64; i += 128) {
        int c = i >> 6, o = i & 63;
        sW1[i] = w1[o * CIN_ + c] * sS[o];
    }
    for (int i = tid; i < 64 * 64; i += 128) {
        int c = i >> 6, o = i & 63;
        sW2[i] = w2[o * 64 + c] * sS[64 + o];
    }
    for (int i = tid; i < 64 * 128; i += 128) {
        int c = i >> 7, o = i & 127;
        sW3[i] = w3[o * 64 + c] * sS[128 + o];
    }
    __syncthreads();

    const int warp = tid >> 5;
    const int lane = tid & 31;
    float* myX = sX + tid * XS;   // this thread's staging row (x, then y)

    const int pbb = CS / (WPB * CPW);             // blocks per batch
    const int b   = blockIdx.x / pbb;
    const int cb  = b * S_ + s0 + (blockIdx.x % pbb) * (WPB * CPW);

    for (int it = 0; it < CPW; it++) {
        const int ci = cb + warp * CPW + it;

        // ---- gather: stage this lane's k-slot input row into SMEM ----
        const int  ig    = g_gidx[(size_t)ci * K_ + lane];
        const bool valid = (ig >= 0);
        const int  ip    = valid ? ig : 0;
        const float* ctr = centers + (size_t)ci * 3;
        const float* p   = xyzs + ((size_t)b * N_ + ip) * 3;
        myX[0] = valid ? (p[0] - ctr[0]) : 0.0f;
        myX[1] = valid ? (p[1] - ctr[1]) : 0.0f;
        myX[2] = valid ? (p[2] - ctr[2]) : 0.0f;
        const float4* f4 = (const float4*)(feats + ((size_t)b * N_ + ip) * F_);
#pragma unroll
        for (int q = 0; q < 16; q++) {
            float4 t = f4[q];
            myX[3 + 4 * q + 0] = valid ? t.x : 0.0f;
            myX[3 + 4 * q + 1] = valid ? t.y : 0.0f;
            myX[3 + 4 * q + 2] = valid ? t.z : 0.0f;
            myX[3 + 4 * q + 3] = valid ? t.w : 0.0f;
        }

        ull acc[32];

        // ---- layer 1: 67 -> 64 ----
#pragma unroll
        for (int t = 0; t < 32; t++) acc[t] = ((const ull*)sB1)[t];
#pragma unroll 1
        for (int c = 0; c < CIN_; c++) step64(acc, myX[c], sW1 + c * 64);
#pragma unroll
        for (int t = 0; t < 32; t++) {
            float lo, hi; upk2(acc[t], lo, hi);
            myX[2 * t]     = fmaxf(lo, 0.0f);
            myX[2 * t + 1] = fmaxf(hi, 0.0f);
        }

        // ---- layer 2: 64 -> 64 ----
#pragma unroll
        for (int t = 0; t < 32; t++) acc[t] = ((const ull*)sB2)[t];
#pragma unroll 1
        for (int c = 0; c < 64; c++) step64(acc, myX[c], sW2 + c * 64);
#pragma unroll
        for (int t = 0; t < 32; t++) {
            float lo, hi; upk2(acc[t], lo, hi);
            myX[2 * t]     = fmaxf(lo, 0.0f);
            myX[2 * t + 1] = fmaxf(hi, 0.0f);
        }

        // ---- layer 3: 64 -> 128 in two halves, relu, warp max over K ----
        float* op = outf + (size_t)ci * 128;
#pragma unroll 1
        for (int h = 0; h < 2; h++) {
#pragma unroll
            for (int t = 0; t < 32; t++) acc[t] = ((const ull*)(sB3 + h * 64))[t];
#pragma unroll 1
            for (int c = 0; c < 64; c++) step64(acc, myX[c], sW3 + c * 128 + h * 64);
#pragma unroll
            for (int t = 0; t < 32; t++) {
                float lo, hi; upk2(acc[t], lo, hi);
                unsigned ulo = __float_as_uint(fmaxf(lo, 0.0f)) & 0x7fffffffu;
                unsigned uhi = __float_as_uint(fmaxf(hi, 0.0f)) & 0x7fffffffu;
                float rlo = __uint_as_float(__reduce_max_sync(0xffffffffu, ulo));
                float rhi = __uint_as_float(__reduce_max_sync(0xffffffffu, uhi));
                if (lane == 0)
                    *(float2*)(op + h * 64 + 2 * t) = make_float2(rlo, rhi);
            }
        }
    }
}

// ---------------------------------------------------------------------------
extern "C" void kernel_launch(void* const* d_in, const int* in_sizes, int n_in,
                              void* d_out, int out_size)
{
    const float* xyzs  = (const float*)d_in[0];
    const float* feats = (const float*)d_in[1];
    const float* w1 = (const float*)d_in[2];
    const float* b1 = (const float*)d_in[3];
    const float* g1 = (const float*)d_in[4];
    const float* bt1= (const float*)d_in[5];
    const float* m1 = (const float*)d_in[6];
    const float* v1 = (const float*)d_in[7];
    const float* w2 = (const float*)d_in[8];
    const float* b2 = (const float*)d_in[9];
    const float* g2 = (const float*)d_in[10];
    const float* bt2= (const float*)d_in[11];
    const float* m2 = (const float*)d_in[12];
    const float* v2 = (const float*)d_in[13];
    const float* w3 = (const float*)d_in[14];
    const float* b3 = (const float*)d_in[15];
    const float* g3 = (const float*)d_in[16];
    const float* bt3= (const float*)d_in[17];
    const float* m3 = (const float*)d_in[18];
    const float* v3 = (const float*)d_in[19];

    float* outc = (float*)d_out;                      // [B,S,3]
    float* outf = outc + (size_t)B_ * S_ * 3;         // [B,S,128]

    // FPS uses 96 KB but requests 192 KB to keep worker CTAs off its 8 SMs.
    const int FPS_SMEM  = 192 * 1024;
    const int BALL_SMEM = N_ * sizeof(float4);                    // 128 KB
    const int MLP_SMEM  = (CIN_ * 64 + 64 * 64 + 64 * 128 + 64 + 64 + 128 + 256
                           + 128 * XS) * sizeof(float);           // ~104 KB

    static cudaStream_t ws = nullptr;
    static cudaEvent_t  evF[CH];
    static cudaEvent_t  evJ;
    if (!ws) {
        cudaStreamCreateWithFlags(&ws, cudaStreamNonBlocking);
        for (int k = 0; k < CH; k++)
            cudaEventCreateWithFlags(&evF[k], cudaEventDisableTiming);
        cudaEventCreateWithFlags(&evJ, cudaEventDisableTiming);
        cudaFuncSetAttribute(fps_kernel,  cudaFuncAttributeMaxDynamicSharedMemorySize, FPS_SMEM);
        cudaFuncSetAttribute(ball_kernel, cudaFuncAttributeMaxDynamicSharedMemorySize, BALL_SMEM);
        cudaFuncSetAttribute(mlp_kernel,  cudaFuncAttributeMaxDynamicSharedMemorySize, MLP_SMEM);
    }

    for (int k = 0; k < CH; k++) {
        fps_kernel<<<B_, FTH, FPS_SMEM>>>(xyzs, outc,
                                          (k == 0) ? 1 : k * CS, (k + 1) * CS,
                                          (k == 0) ? 1 : 0);
        cudaEventRecord(evF[k], 0);
        cudaStreamWaitEvent(ws, evF[k], 0);
        ball_kernel<<<B_ * (CS / 16), 512, BALL_SMEM, ws>>>(xyzs, outc, k * CS);
        mlp_kernel <<<B_ * (CS / (WPB * CPW)), 128, MLP_SMEM, ws>>>(
            xyzs, feats,
            w1, b1, g1, bt1, m1, v1,
            w2, b2, g2, bt2, m2, v2,
            w3, b3, g3, bt3, m3, v3,
            outc, outf, k * CS);
    }
    cudaEventRecord(evJ, ws);
    cudaStreamWaitEvent(0, evJ, 0);
}